// round 15
// baseline (speedup 1.0000x reference)
#include <cuda_runtime.h>
#include <cuda_bf16.h>
#include <cstdint>

// ---------------- problem dims ----------------
#define Nn 1024
#define Ee 8192
#define BN 4096    // B*N
#define BE 32768   // B*E

// ---------------- device scratch ----------------
#define OFF_NEB    ((size_t)0)                       // node_enc bfp
#define OFF_NEF    (OFF_NEB + (size_t)BN*128)        // node_enc f32
#define OFF_NF1F   (OFF_NEF + (size_t)BN*128)        // nf1 f32
#define OFF_PC     (OFF_NF1F + (size_t)BN*128)       // neb@pp0a f32
#define OFF_AGG0   (OFF_PC + (size_t)BN*128)
#define OFF_AGG1   (OFF_AGG0 + (size_t)BN*128)       // adjacent to agg0
#define OFF_PRS    (OFF_AGG1 + (size_t)BN*128)       // [BN,256] f32 (x@Wr | x@Ws)
#define OFF_PRPSPA (OFF_PRS + (size_t)BN*256)        // [BN,256] f32 step0
#define OFF_PRPSPB (OFF_PRPSPA + (size_t)BN*256)     // [BN,256] f32 step1
#define OFF_EC     (OFF_PRPSPB + (size_t)BN*256)     // [BE,128] f32
#define ARENA_U32  (OFF_EC + (size_t)BE*128)

__device__ uint32_t g_arena[ARENA_U32];
__device__ int g_recv[BE];
__device__ int g_send[BE];
__device__ float g_zero[256];

// split/transposed weights [n][kpad] bf16, 12 matrices
#define WT_TOTAL 221184
__device__ __nv_bfloat16 g_whi[WT_TOTAL];
__device__ __nv_bfloat16 g_wlo[WT_TOTAL];

// ---------------- helpers ----------------
__device__ __forceinline__ uint32_t smem_u32(const void* p) {
    uint32_t a;
    asm("{ .reg .u64 t; cvta.to.shared.u64 t, %1; cvt.u32.u64 %0, t; }" : "=r"(a) : "l"(p));
    return a;
}

#define LDMX4(r, ad) \
    asm volatile("ldmatrix.sync.aligned.m8n8.x4.shared.b16 {%0,%1,%2,%3}, [%4];" \
        : "=r"((r)[0]), "=r"((r)[1]), "=r"((r)[2]), "=r"((r)[3]) : "r"(ad))

#define MMA16816(d, av, bv) \
    asm volatile("mma.sync.aligned.m16n8k16.row.col.f32.bf16.bf16.f32 " \
        "{%0,%1,%2,%3},{%4,%5,%6,%7},{%8,%9},{%0,%1,%2,%3};" \
        : "+f"((d)[0]), "+f"((d)[1]), "+f"((d)[2]), "+f"((d)[3]) \
        : "r"((av)[0]), "r"((av)[1]), "r"((av)[2]), "r"((av)[3]), \
          "r"((bv)[0]), "r"((bv)[1]))

#define CP_ASYNC16(sa, gp) \
    asm volatile("cp.async.cg.shared.global [%0], [%1], 16;" :: "r"(sa), "l"(gp))
#define CP_COMMIT()  asm volatile("cp.async.commit_group;" ::: "memory")
#define CP_WAIT1()   asm volatile("cp.async.wait_group 1;" ::: "memory")
#define CP_WAIT0()   asm volatile("cp.async.wait_group 0;" ::: "memory")

#define REDV2(ptr, v0, v1) \
    asm volatile("red.global.add.v2.f32 [%0], {%1, %2};" \
        :: "l"(ptr), "f"(v0), "f"(v1) : "memory")
#define REDV4(ptr, v0, v1, v2, v3) \
    asm volatile("red.global.add.v4.f32 [%0], {%1, %2, %3, %4};" \
        :: "l"(ptr), "f"(v0), "f"(v1), "f"(v2), "f"(v3) : "memory")

__device__ __forceinline__ uint32_t packbfp(float v) {
    __nv_bfloat16 h = __float2bfloat16(v);
    float hf = __bfloat162float(h);
    __nv_bfloat16 l = __float2bfloat16(v - hf);
    return (uint32_t)__bfloat16_as_ushort(h) | ((uint32_t)__bfloat16_as_ushort(l) << 16);
}

// ---- 32-col-warp, 2 m-tiles per warp (edge_mega) ----
__device__ __forceinline__ void mma_span_mt2(
    uint32_t aHi, uint32_t aLo, uint32_t bHi, uint32_t bLo,
    int astr, int bstr, int nk, float (*acc0)[4], float (*acc1)[4],
    int tile0, int wn, int lane)
{
    for (int ks = 0; ks < nk; ks++) {
        uint32_t bh[8], bl[8];
        #pragma unroll
        for (int np = 0; np < 2; np++) {
            int n = wn * 32 + np * 16 + ((lane >> 4) << 3) + (lane & 7);
            int koff = ((lane >> 3) & 1) << 3;
            uint32_t ad = bHi + n * bstr + (ks * 16 + koff) * 2;
            LDMX4(&bh[np * 4], ad);
            LDMX4(&bl[np * 4], ad + (bLo - bHi));
        }
        int koff = (lane >> 4) << 3;
        uint32_t ah0[4], al0[4], ah1[4], al1[4];
        {
            int r = tile0 * 16 + (lane & 15);
            uint32_t ad = aHi + r * astr + (ks * 16 + koff) * 2;
            LDMX4(ah0, ad);
            LDMX4(al0, ad + (aLo - aHi));
        }
        {
            int r = (tile0 + 1) * 16 + (lane & 15);
            uint32_t ad = aHi + r * astr + (ks * 16 + koff) * 2;
            LDMX4(ah1, ad);
            LDMX4(al1, ad + (aLo - aHi));
        }
        #pragma unroll
        for (int st = 0; st < 4; st++) {
            MMA16816(acc0[st], ah0, &bh[st * 2]);
            MMA16816(acc1[st], ah1, &bh[st * 2]);
            MMA16816(acc0[st], ah0, &bl[st * 2]);
            MMA16816(acc1[st], ah1, &bl[st * 2]);
            MMA16816(acc0[st], al0, &bh[st * 2]);
            MMA16816(acc1[st], al1, &bh[st * 2]);
        }
    }
}

// ---- 16-col-warp 3-pass MMA (512-thread kernels): wn in 0..7 ----
__device__ __forceinline__ void mma_span16(
    uint32_t aHi, uint32_t aLo, uint32_t bHi, uint32_t bLo,
    int astr, int bstr, int nk, float (*acc)[4], int tile, int wn, int lane)
{
    for (int ks = 0; ks < nk; ks++) {
        uint32_t bh[4], bl[4];
        int n = wn * 16 + ((lane >> 4) << 3) + (lane & 7);
        int koff = ((lane >> 3) & 1) << 3;
        uint32_t ad = bHi + n * bstr + (ks * 16 + koff) * 2;
        LDMX4(bh, ad);
        LDMX4(bl, ad + (bLo - bHi));
        int r = tile * 16 + (lane & 15);
        int koff2 = (lane >> 4) << 3;
        uint32_t ad2 = aHi + r * astr + (ks * 16 + koff2) * 2;
        uint32_t ah[4], al[4];
        LDMX4(ah, ad2);
        LDMX4(al, ad2 + (aLo - aHi));
        #pragma unroll
        for (int st = 0; st < 2; st++) {
            MMA16816(acc[st], ah, &bh[st * 2]);
            MMA16816(acc[st], ah, &bl[st * 2]);
            MMA16816(acc[st], al, &bh[st * 2]);
        }
    }
}

// async weight load with K-window (cp.async, caller commits/waits)
__device__ __forceinline__ void load_Bw_cp(uint32_t sbase, int plane,
    const __nv_bfloat16* Bhi, const __nv_bfloat16* Blo,
    int nrows, int kwin, int fullK, int k0, int bstr, int tid, int nth)
{
    int kg = kwin >> 3;
    int per = nrows * kg;
    for (int item = tid; item < per; item += nth) {
        int n = item / kg, g = item - n * kg;
        size_t goff = (size_t)n * fullK + k0 + (g << 3);
        uint32_t so = sbase + n * bstr + (g << 4);
        CP_ASYNC16(so, Bhi + goff);
        CP_ASYNC16(so + plane, Blo + goff);
    }
}

// 32-col-warp epilogue (edge_mega): relu(acc+bias) -> repack A planes
__device__ __forceinline__ void epi_repack2(char* smem, int astr, int aplane,
    float (*acc)[4], int m0, int tile,
    const float* bias, int wn, int lane)
{
    #pragma unroll
    for (int st = 0; st < 4; st++) {
        int n = wn * 32 + st * 8 + ((lane & 3) << 1);
        float b0 = __ldg(bias + n), b1 = __ldg(bias + n + 1);
        int r0 = tile * 16 + (lane >> 2);
        #pragma unroll
        for (int h = 0; h < 2; h++) {
            int r = r0 + h * 8;
            float s0 = fmaxf(acc[st][h * 2 + 0] + b0, 0.f);
            float s1 = fmaxf(acc[st][h * 2 + 1] + b1, 0.f);
            uint32_t p0 = packbfp(s0), p1 = packbfp(s1);
            int off = r * astr + n * 2;
            *(uint32_t*)(smem + off) = (p0 & 0xffffu) | (p1 << 16);
            *(uint32_t*)(smem + aplane + off) = (p0 >> 16) | (p1 & 0xffff0000u);
            acc[st][h * 2 + 0] = 0.f;
            acc[st][h * 2 + 1] = 0.f;
        }
    }
}

// 16-col-warp epilogue (+optional f32 out, +optional bfp out)
__device__ __forceinline__ void epi_repack16(char* smem, int astr, int aplane,
    float (*acc)[4], int m0, int tile,
    const float* bias, const float* resid, float* outf, uint32_t* outb,
    int wn, int lane)
{
    #pragma unroll
    for (int st = 0; st < 2; st++) {
        int n = wn * 16 + st * 8 + ((lane & 3) << 1);
        float b0 = __ldg(bias + n), b1 = __ldg(bias + n + 1);
        int r0 = tile * 16 + (lane >> 2);
        #pragma unroll
        for (int h = 0; h < 2; h++) {
            int r = r0 + h * 8;
            float s0 = acc[st][h * 2 + 0] + b0;
            float s1 = acc[st][h * 2 + 1] + b1;
            if (resid) {
                float2 rv = *(const float2*)(resid + (((size_t)(m0 + r)) << 7) + n);
                s0 += rv.x; s1 += rv.y;
            }
            s0 = fmaxf(s0, 0.f); s1 = fmaxf(s1, 0.f);
            if (outf) *(float2*)(outf + (((size_t)(m0 + r)) << 7) + n) = make_float2(s0, s1);
            uint32_t p0 = packbfp(s0), p1 = packbfp(s1);
            if (outb) *(uint2*)(outb + (((size_t)(m0 + r)) << 7) + n) = make_uint2(p0, p1);
            int off = r * astr + n * 2;
            *(uint32_t*)(smem + off) = (p0 & 0xffffu) | (p1 << 16);
            *(uint32_t*)(smem + aplane + off) = (p0 >> 16) | (p1 & 0xffff0000u);
            acc[st][h * 2 + 0] = 0.f;
            acc[st][h * 2 + 1] = 0.f;
        }
    }
}

// write acc f32 (16-col warps)
__device__ __forceinline__ void write_accf16(float (*acc)[4], int m0, int tile,
    int wn, int lane, float* out, int nbase, int ldo)
{
    #pragma unroll
    for (int st = 0; st < 2; st++) {
        int n = nbase + wn * 16 + st * 8 + ((lane & 3) << 1);
        int r0 = tile * 16 + (lane >> 2);
        #pragma unroll
        for (int h = 0; h < 2; h++) {
            int m = m0 + r0 + h * 8;
            *(float2*)(out + (size_t)m * ldo + n) =
                make_float2(acc[st][h * 2 + 0], acc[st][h * 2 + 1]);
            acc[st][h * 2 + 0] = 0.f;
            acc[st][h * 2 + 1] = 0.f;
        }
    }
}

// ---------------- aux kernels ----------------
__global__ void extract_idx2_kernel(const float* __restrict__ Rr,
                                    const float* __restrict__ Rs,
                                    int* __restrict__ recv, int* __restrict__ send)
{
    int row = blockIdx.x * 8 + (threadIdx.x >> 5);
    int lane = threadIdx.x & 31;
    const float* R = (row < BE) ? Rr : Rs;
    int r = (row < BE) ? row : row - BE;
    const float4* p = (const float4*)(R + (size_t)r * Nn);
    int found = -1;
    #pragma unroll
    for (int i = 0; i < 4; i++) {
        int q = lane + i * 32;
        float4 v = p[q];
        if (v.x > 0.5f) found = q * 4 + 0;
        if (v.y > 0.5f) found = q * 4 + 1;
        if (v.z > 0.5f) found = q * 4 + 2;
        if (v.w > 0.5f) found = q * 4 + 3;
    }
    if (__ballot_sync(0xFFFFFFFFu, found >= 0) == 0u) {
        #pragma unroll
        for (int i = 4; i < 8; i++) {
            int q = lane + i * 32;
            float4 v = p[q];
            if (v.x > 0.5f) found = q * 4 + 0;
            if (v.y > 0.5f) found = q * 4 + 1;
            if (v.z > 0.5f) found = q * 4 + 2;
            if (v.w > 0.5f) found = q * 4 + 3;
        }
    }
    #pragma unroll
    for (int o = 16; o; o >>= 1) found = max(found, __shfl_xor_sync(0xFFFFFFFFu, found, o));
    if (lane == 0) {
        found = max(found, 0);
        if (row < BE) recv[r] = found; else send[r] = found;
    }
}

// matrices: 0 ne0 1 ne1 2 ne2 3 eers(R256) 4 ee1 5 ee2 6 ep_e 7 ep_rs(R256)
//           8 np(K256) 9 pp0a 10 pp0b 11 pp1
struct PArg { const float* W[12]; };
__constant__ int c_Ks[12]  = {32,128,128, 32,128,128,128,128,256,128,128,128};
__constant__ int c_Kps[12] = {64,128,128, 64,128,128,128,128,256,128,128,128};
__constant__ int c_Rs[12]  = {128,128,128,256,128,128,128,256,128,128,128,128};
__constant__ int c_r0a[12] = {0,0,0,0,0,0,0,128,0,0,128,0};
__constant__ int c_r0b[12] = {0,0,0,32,0,0,0,256,0,0,0,0};
__constant__ int c_off[12] = {0,8192,24576,40960,57344,73728,90112,106496,139264,172032,188416,204800};

__global__ void prep_weights(PArg a, __nv_bfloat16* __restrict__ hi, __nv_bfloat16* __restrict__ lo)
{
    int mid = blockIdx.x;
    int K = c_Ks[mid], Kp = c_Kps[mid], R = c_Rs[mid];
    int r0a = c_r0a[mid], r0b = c_r0b[mid];
    const float* W = a.W[mid];
    __nv_bfloat16* dh = hi + c_off[mid];
    __nv_bfloat16* dl = lo + c_off[mid];
    int total = R * Kp;
    for (int i = threadIdx.x + blockIdx.y * blockDim.x; i < total; i += blockDim.x * gridDim.y) {
        int n = i / Kp, k = i - n * Kp;
        int col = n & 127;
        int r0 = (n >> 7) ? r0b : r0a;
        float v = (k < K) ? W[(size_t)(r0 + k) * 128 + col] : 0.f;
        __nv_bfloat16 h = __float2bfloat16(v);
        dh[i] = h;
        dl[i] = __float2bfloat16(v - __bfloat162float(h));
    }
}

// step-1 scatter: 4 h-values per thread, vector reduction
__global__ void fused_scatter_kernel(const float* __restrict__ ec,
                                     const float* __restrict__ prpsp,
                                     const int* __restrict__ recv,
                                     const int* __restrict__ send,
                                     const float* __restrict__ bias,
                                     float* __restrict__ agg)
{
    int t = blockIdx.x * blockDim.x + threadIdx.x;   // BE*32
    if (t >= BE * 32) return;
    int e = t >> 5, q = t & 31;
    int h = q << 2;
    int bo = (e >> 13) << 10;
    int r = __ldg(recv + e) + bo, s = __ldg(send + e) + bo;
    float4 ev = *(const float4*)(ec + ((size_t)e << 7) + h);
    float4 pr = *(const float4*)(prpsp + (size_t)r * 256 + h);
    float4 ps = *(const float4*)(prpsp + (size_t)s * 256 + 128 + h);
    float4 bb = *(const float4*)(bias + h);
    float v0 = fmaxf(ev.x + pr.x + ps.x + bb.x, 0.f);
    float v1 = fmaxf(ev.y + pr.y + ps.y + bb.y, 0.f);
    float v2 = fmaxf(ev.z + pr.z + ps.z + bb.z, 0.f);
    float v3 = fmaxf(ev.w + pr.w + ps.w + bb.w, 0.f);
    REDV4(agg + (size_t)r * 128 + h, v0, v1, v2, v3);
}

// ---------------- node_mega: eer,ees,ne0..ne2,epr,eps,pc (512 thr, ping-pong) ----------------
#define NM_STR   272
#define NM_ALO   (32 * NM_STR)
#define NM_B0    (2 * NM_ALO)
#define NM_BPL   (128 * NM_STR)
#define NM_SLOT  (2 * NM_BPL)
#define NM_SMEM  (NM_B0 + 2 * NM_SLOT)     // 156672

struct NodeArg {
    const float* x;
    const __nv_bfloat16 *eerh,*eerl,*eesh,*eesl;
    const __nv_bfloat16 *w0h,*w0l,*w1h,*w1l,*w2h,*w2l,*eprh,*eprl,*epsh,*epsl,*pqh,*pql;
    const float *b0,*b1,*b2;
    uint32_t* neb; float* nef; float* prs; float* prpsp; float* pc;
};

__global__ __launch_bounds__(512, 1) void node_mega(NodeArg a)
{
    extern __shared__ char smem[];
    const uint32_t sb = smem_u32(smem);
    const int tid = threadIdx.x;
    const int wid = tid >> 5, lane = tid & 31;
    const int wm = wid & 1, wn = wid >> 1;     // 2m x 8n warp grid (16 cols/warp)
    const int m0 = blockIdx.x * 32;

    const uint32_t sA = sb + NM_B0;
    const uint32_t sB = sb + NM_B0 + NM_SLOT;

    float acc[2][4];
    #pragma unroll
    for (int st = 0; st < 2; st++)
        #pragma unroll
        for (int r = 0; r < 4; r++) acc[st][r] = 0.f;

    load_Bw_cp(sA, NM_BPL, a.eerh, a.eerl, 128, 64, 64, 0, NM_STR, tid, 512); CP_COMMIT();
    load_Bw_cp(sB, NM_BPL, a.eesh, a.eesl, 128, 64, 64, 0, NM_STR, tid, 512); CP_COMMIT();

    // A <- x (K=32 pad 64): 512 items, one per thread
    {
        int r = tid >> 4, g = tid & 15;
        int kc = g << 2;
        uint32_t p0 = 0, p1 = 0, p2 = 0, p3 = 0;
        if (kc < 32) {
            float4 v = *(const float4*)(a.x + (size_t)(m0 + r) * 32 + kc);
            p0 = packbfp(v.x); p1 = packbfp(v.y); p2 = packbfp(v.z); p3 = packbfp(v.w);
        }
        uint32_t hi01 = (p0 & 0xffffu) | (p1 << 16);
        uint32_t hi23 = (p2 & 0xffffu) | (p3 << 16);
        uint32_t lo01 = (p0 >> 16) | (p1 & 0xffff0000u);
        uint32_t lo23 = (p2 >> 16) | (p3 & 0xffff0000u);
        int off = r * NM_STR + g * 8;
        *(uint2*)(smem + off) = make_uint2(hi01, hi23);
        *(uint2*)(smem + NM_ALO + off) = make_uint2(lo01, lo23);
    }

    // P0: eer -> prs[:,0:128]
    CP_WAIT1(); __syncthreads();
    mma_span16(sb, sb + NM_ALO, sA, sA + NM_BPL, NM_STR, NM_STR, 4, acc, wm, wn, lane);
    __syncthreads();
    write_accf16(acc, m0, wm, wn, lane, a.prs, 0, 256);
    load_Bw_cp(sA, NM_BPL, a.w0h, a.w0l, 128, 64, 64, 0, NM_STR, tid, 512); CP_COMMIT();

    // P1: ees -> prs[:,128:256]
    CP_WAIT1(); __syncthreads();
    mma_span16(sb, sb + NM_ALO, sB, sB + NM_BPL, NM_STR, NM_STR, 4, acc, wm, wn, lane);
    __syncthreads();
    write_accf16(acc, m0, wm, wn, lane, a.prs, 128, 256);
    load_Bw_cp(sB, NM_BPL, a.w1h, a.w1l, 128, 128, 128, 0, NM_STR, tid, 512); CP_COMMIT();

    // P2: ne0
    CP_WAIT1(); __syncthreads();
    mma_span16(sb, sb + NM_ALO, sA, sA + NM_BPL, NM_STR, NM_STR, 4, acc, wm, wn, lane);
    __syncthreads();
    epi_repack16(smem, NM_STR, NM_ALO, acc, m0, wm, a.b0, nullptr, nullptr, nullptr, wn, lane);
    load_Bw_cp(sA, NM_BPL, a.w2h, a.w2l, 128, 128, 128, 0, NM_STR, tid, 512); CP_COMMIT();

    // P3: ne1
    CP_WAIT1(); __syncthreads();
    mma_span16(sb, sb + NM_ALO, sB, sB + NM_BPL, NM_STR, NM_STR, 8, acc, wm, wn, lane);
    __syncthreads();
    epi_repack16(smem, NM_STR, NM_ALO, acc, m0, wm, a.b1, nullptr, nullptr, nullptr, wn, lane);
    load_Bw_cp(sB, NM_BPL, a.eprh, a.eprl, 128, 128, 128, 0, NM_STR, tid, 512); CP_COMMIT();

    // P4: ne2 -> neb/nef
    CP_WAIT1(); __syncthreads();
    mma_span16(sb, sb + NM_ALO, sA, sA + NM_BPL, NM_STR, NM_STR, 8, acc, wm, wn, lane);
    __syncthreads();
    epi_repack16(smem, NM_STR, NM_ALO, acc, m0, wm, a.b2, nullptr, a.nef, a.neb, wn, lane);
    load_Bw_cp(sA, NM_BPL, a.epsh, a.epsl, 128, 128, 128, 0, NM_STR, tid, 512); CP_COMMIT();

    // P5: epr -> prpspA[:,0:128]
    CP_WAIT1(); __syncthreads();
    mma_span16(sb, sb + NM_ALO, sB, sB + NM_BPL, NM_STR, NM_STR, 8, acc, wm, wn, lane);
    __syncthreads();
    write_accf16(acc, m0, wm, wn, lane, a.prpsp, 0, 256);
    load_Bw_cp(sB, NM_BPL, a.pqh, a.pql, 128, 128, 128, 0, NM_STR, tid, 512); CP_COMMIT();

    // P6: eps -> prpspA[:,128:256]
    CP_WAIT1(); __syncthreads();
    mma_span16(sb, sb + NM_ALO, sA, sA + NM_BPL, NM_STR, NM_STR, 8, acc, wm, wn, lane);
    __syncthreads();
    write_accf16(acc, m0, wm, wn, lane, a.prpsp, 128, 256);

    // P7: pc
    CP_WAIT0(); __syncthreads();
    mma_span16(sb, sb + NM_ALO, sB, sB + NM_BPL, NM_STR, NM_STR, 8, acc, wm, wn, lane);
    __syncthreads();
    write_accf16(acc, m0, wm, wn, lane, a.pc, 0, 128);
}

// ---------------- edge_mega: 128-row tiles, 512 thr, 4m x 4n warps ----------------
#define EM_STR   272
#define EM_APL   (128 * EM_STR)
#define EM_B0    (2 * EM_APL)
#define EM_BPL   (128 * EM_STR)
#define EM_SLOT  (2 * EM_BPL)
#define EM_SMEM  (EM_B0 + 2 * EM_SLOT)     // 208896

struct EdgeArg {
    const float* prs; const int* recv; const int* send; const float* eeb0;
    const __nv_bfloat16 *w1h,*w1l,*w2h,*w2l,*weh,*wel;
    const float *b1,*b2;
    const float* prpsp; const float* epb;
    float* ec; float* agg;
};

__global__ __launch_bounds__(512, 1) void edge_mega(EdgeArg a)
{
    extern __shared__ char smem[];
    const uint32_t sb = smem_u32(smem);
    const int tid = threadIdx.x;
    const int wid = tid >> 5, lane = tid & 31;
    const int wm = wid & 3, wn = wid >> 2;
    const int m0 = blockIdx.x * 128;

    const uint32_t sA = sb + EM_B0;
    const uint32_t sB = sb + EM_B0 + EM_SLOT;

    float acc[2][4][4];
    #pragma unroll
    for (int mt = 0; mt < 2; mt++)
        #pragma unroll
        for (int st = 0; st < 4; st++)
            #pragma unroll
            for (int r = 0; r < 4; r++) acc[mt][st][r] = 0.f;

    load_Bw_cp(sA, EM_BPL, a.w1h, a.w1l, 128, 128, 128, 0, EM_STR, tid, 512); CP_COMMIT();
    load_Bw_cp(sB, EM_BPL, a.w2h, a.w2l, 128, 128, 128, 0, EM_STR, tid, 512); CP_COMMIT();

    // A <- edge layer0 on the fly
    #pragma unroll
    for (int it = 0; it < 8; it++) {
        int item = tid + (it << 9);
        int r = item >> 5, g = item & 31;
        int kc = g << 2;
        int m = m0 + r;
        int bo = (m >> 13) << 10;
        int rr = __ldg(a.recv + m) + bo, ss = __ldg(a.send + m) + bo;
        float4 pr = *(const float4*)(a.prs + (size_t)rr * 256 + kc);
        float4 ps = *(const float4*)(a.prs + (size_t)ss * 256 + 128 + kc);
        float4 bb = *(const float4*)(a.eeb0 + kc);
        uint32_t p0 = packbfp(fmaxf(pr.x + ps.x + bb.x, 0.f));
        uint32_t p1 = packbfp(fmaxf(pr.y + ps.y + bb.y, 0.f));
        uint32_t p2 = packbfp(fmaxf(pr.z + ps.z + bb.z, 0.f));
        uint32_t p3 = packbfp(fmaxf(pr.w + ps.w + bb.w, 0.f));
        uint32_t hi01 = (p0 & 0xffffu) | (p1 << 16);
        uint32_t hi23 = (p2 & 0xffffu) | (p3 << 16);
        uint32_t lo01 = (p0 >> 16) | (p1 & 0xffff0000u);
        uint32_t lo23 = (p2 >> 16) | (p3 & 0xffff0000u);
        int off = r * EM_STR + g * 8;
        *(uint2*)(smem + off) = make_uint2(hi01, hi23);
        *(uint2*)(smem + EM_APL + off) = make_uint2(lo01, lo23);
    }

    // phase 1: ee1 (sA)
    CP_WAIT1(); __syncthreads();
    mma_span_mt2(sb, sb + EM_APL, sA, sA + EM_BPL, EM_STR, EM_STR, 8,
                 acc[0], acc[1], wm * 2, wn, lane);
    __syncthreads();
    #pragma unroll
    for (int mt = 0; mt < 2; mt++)
        epi_repack2(smem, EM_STR, EM_APL, acc[mt], m0, wm * 2 + mt, a.b1, wn, lane);
    load_Bw_cp(sA, EM_BPL, a.weh, a.wel, 128, 128, 128, 0, EM_STR, tid, 512); CP_COMMIT();

    // phase 2: ee2 (sB)
    CP_WAIT1(); __syncthreads();
    mma_span_mt2(sb, sb + EM_APL, sB, sB + EM_BPL, EM_STR, EM_STR, 8,
                 acc[0], acc[1], wm * 2, wn, lane);
    __syncthreads();
    #pragma unroll
    for (int mt = 0; mt < 2; mt++)
        epi_repack2(smem, EM_STR, EM_APL, acc[mt], m0, wm * 2 + mt, a.b2, wn, lane);

    // phase 3: ec (sA)
    CP_WAIT0(); __syncthreads();
    mma_span_mt2(sb, sb + EM_APL, sA, sA + EM_BPL, EM_STR, EM_STR, 8,
                 acc[0], acc[1], wm * 2, wn, lane);

    // epilogue: write ec + fused step-0 scatter (vector reductions)
    #pragma unroll
    for (int mt = 0; mt < 2; mt++) {
        int row0 = m0 + (wm * 2 + mt) * 16 + (lane >> 2);
        #pragma unroll
        for (int st = 0; st < 4; st++) {
            int n = wn * 32 + st * 8 + ((lane & 3) << 1);
            float e0b = __ldg(a.epb + n), e1b = __ldg(a.epb + n + 1);
            #pragma unroll
            for (int h = 0; h < 2; h++) {
                int m = row0 + h * 8;
                float e0 = acc[mt][st][h * 2 + 0];
                float e1 = acc[mt][st][h * 2 + 1];
                *(float2*)(a.ec + ((size_t)m << 7) + n) = make_float2(e0, e1);
                int bo = (m >> 13) << 10;
                int r_ = __ldg(a.recv + m) + bo, s_ = __ldg(a.send + m) + bo;
                float2 pr = *(const float2*)(a.prpsp + (size_t)r_ * 256 + n);
                float2 ps = *(const float2*)(a.prpsp + (size_t)s_ * 256 + 128 + n);
                float v0 = fmaxf(e0 + pr.x + ps.x + e0b, 0.f);
                float v1 = fmaxf(e1 + pr.y + ps.y + e1b, 0.f);
                REDV2(a.agg + (size_t)r_ * 128 + n, v0, v1);
            }
        }
    }
}

// ---------------- np_prpsp / tail (512 threads, ping-pong, K-chunked np) ----------------
#define NSTR   528
#define N_ALO  (32 * NSTR)
#define N_B0   (2 * N_ALO)
#define N_BPL  (128 * 272)
#define N_SLOT (2 * N_BPL)
#define NT_SMEM (N_B0 + 2 * N_SLOT)        // 173056

__device__ __forceinline__ void load_A_npagg(char* smem, int m0,
    const uint32_t* neb, const float* agg, int tid)
{
    #pragma unroll
    for (int it = 0; it < 4; it++) {
        int item = tid + (it << 9);
        int r = item >> 6, g = item & 63;
        int kc = g << 2;
        int m = m0 + r;
        uint32_t p0, p1, p2, p3;
        if (kc < 128) {
            uint4 v = *(const uint4*)(neb + ((size_t)m << 7) + kc);
            p0 = v.x; p1 = v.y; p2 = v.z; p3 = v.w;
        } else {
            float4 v = *(const float4*)(agg + ((size_t)m << 7) + (kc - 128));
            p0 = packbfp(v.x); p1 = packbfp(v.y); p2 = packbfp(v.z); p3 = packbfp(v.w);
        }
        uint32_t hi01 = (p0 & 0xffffu) | (p1 << 16);
        uint32_t hi23 = (p2 & 0xffffu) | (p3 << 16);
        uint32_t lo01 = (p0 >> 16) | (p1 & 0xffff0000u);
        uint32_t lo23 = (p2 >> 16) | (p3 & 0xffff0000u);
        int off = r * NSTR + g * 8;
        *(uint2*)(smem + off) = make_uint2(hi01, hi23);
        *(uint2*)(smem + N_ALO + off) = make_uint2(lo01, lo23);
    }
}

__global__ __launch_bounds__(512, 1) void np_prpsp_kernel(
    const uint32_t* __restrict__ neb, const float* __restrict__ agg,
    const float* __restrict__ resid,
    const __nv_bfloat16* __restrict__ npHi, const __nv_bfloat16* __restrict__ npLo,
    const float* __restrict__ npb,
    const __nv_bfloat16* __restrict__ epHi, const __nv_bfloat16* __restrict__ epLo,
    float* __restrict__ nf_out, float* __restrict__ prpsp_out)
{
    extern __shared__ char smem[];
    const uint32_t sb = smem_u32(smem);
    const int tid = threadIdx.x;
    const int wid = tid >> 5, lane = tid & 31;
    const int wm = wid & 1, wn = wid >> 1;
    const int m0 = blockIdx.x * 32;

    const uint32_t sA = sb + N_B0;
    const uint32_t sB = sb + N_B0 + N_SLOT;

    float acc[2][4];
    #pragma unroll
    for (int st = 0; st < 2; st++)
        #pragma unroll
        for (int r = 0; r < 4; r++) acc[st][r] = 0.f;

    load_Bw_cp(sA, N_BPL, npHi, npLo, 128, 128, 256, 0,   272, tid, 512); CP_COMMIT();
    load_Bw_cp(sB, N_BPL, npHi, npLo, 128, 128, 256, 128, 272, tid, 512); CP_COMMIT();

    load_A_npagg(smem, m0, neb, agg, tid);

    CP_WAIT1(); __syncthreads();
    mma_span16(sb, sb + N_ALO, sA, sA + N_BPL, NSTR, 272, 8, acc, wm, wn, lane);
    __syncthreads();
    load_Bw_cp(sA, N_BPL, epHi, epLo, 128, 128, 128, 0, 272, tid, 512); CP_COMMIT();
    CP_WAIT1(); __syncthreads();
    mma_span16(sb + 256, sb + N_ALO + 256, sB, sB + N_BPL, NSTR, 272, 8, acc, wm, wn, lane);
    __syncthreads();
    epi_repack16(smem, NSTR, N_ALO, acc, m0, wm, npb, resid, nf_out, nullptr, wn, lane);
    load_Bw_cp(sB, N_BPL, epHi + 128 * 128, epLo + 128 * 128, 128, 128, 128, 0, 272, tid, 512); CP_COMMIT();

    CP_WAIT1(); __syncthreads();
    mma_span16(sb, sb + N_ALO, sA, sA + N_BPL, NSTR, 272, 8, acc, wm, wn, lane);
    __syncthreads();
    write_accf16(acc, m0, wm, wn, lane, prpsp_out, 0, 256);

    CP_WAIT0(); __syncthreads();
    mma_span16(sb, sb + N_ALO, sB, sB + N_BPL, NSTR, 272, 8, acc, wm, wn, lane);
    __syncthreads();
    write_accf16(acc, m0, wm, wn, lane, prpsp_out, 128, 256);
}

__global__ __launch_bounds__(512, 1) void tail_kernel(
    const uint32_t* __restrict__ neb, const float* __restrict__ agg1,
    const float* __restrict__ nf1,
    const __nv_bfloat16* __restrict__ npHi, const __nv_bfloat16* __restrict__ npLo,
    const float* __restrict__ npb,
    const float* __restrict__ pc,
    const __nv_bfloat16* __restrict__ p0bHi, const __nv_bfloat16* __restrict__ p0bLo,
    const float* __restrict__ ppb0,
    const __nv_bfloat16* __restrict__ p1Hi, const __nv_bfloat16* __restrict__ p1Lo,
    const float* __restrict__ ppb1,
    const float* __restrict__ ppW2, const float* __restrict__ ppb2,
    float* __restrict__ out)
{
    extern __shared__ char smem[];
    const uint32_t sb = smem_u32(smem);
    const int tid = threadIdx.x;
    const int wid = tid >> 5, lane = tid & 31;
    const int wm = wid & 1, wn = wid >> 1;
    const int m0 = blockIdx.x * 32;

    const uint32_t sA = sb + N_B0;
    const uint32_t sB = sb + N_B0 + N_SLOT;

    float acc[2][4];
    #pragma unroll
    for (int st = 0; st < 2; st++)
        #pragma unroll
        for (int r = 0; r < 4; r++) acc[st][r] = 0.f;

    load_Bw_cp(sA, N_BPL, npHi, npLo, 128, 128, 256, 0,   272, tid, 512); CP_COMMIT();
    load_Bw_cp(sB, N_BPL, npHi, npLo, 128, 128, 256, 128, 272, tid, 512); CP_COMMIT();

    load_A_npagg(smem, m0, neb, agg1, tid);

    CP_WAIT1(); __syncthreads();
    mma_span16(sb, sb + N_ALO, sA, sA + N_BPL, NSTR, 272, 8, acc, wm, wn, lane);
    __syncthreads();
    load_Bw_cp(sA, N_BPL, p0bHi, p0bLo, 128, 128, 128, 0, 272, tid, 512); CP_COMMIT();
    CP_WAIT1(); __syncthreads();
    mma_span16(sb + 256, sb + N_ALO + 256, sB, sB + N_BPL, NSTR, 272, 8, acc, wm, wn, lane);
    __syncthreads();
    epi_repack16(smem, NSTR, N_ALO, acc, m0, wm, npb, nf1, nullptr, nullptr, wn, lane);
    load_Bw_cp(sB, N_BPL, p1Hi, p1Lo, 128, 128, 128, 0, 272, tid, 512); CP_COMMIT();

    CP_WAIT1(); __syncthreads();
    mma_span16(sb, sb + N_ALO, sA, sA + N_BPL, NSTR, 272, 8, acc, wm, wn, lane);
    __syncthreads();
    epi_repack16(smem, NSTR, N_ALO, acc, m0, wm, ppb0, pc, nullptr, nullptr, wn, lane);

    CP_WAIT0(); __syncthreads();
    mma_span16(sb, sb + N_ALO, sB, sB + N_BPL, NSTR, 272, 8, acc, wm, wn, lane);
    __syncthreads();
    float* stage = (float*)(smem + N_B0);
    #pragma unroll
    for (int st = 0; st < 2; st++) {
        int n = wn * 16 + st * 8 + ((lane & 3) << 1);
        float b0 = __ldg(ppb1 + n), b1 = __ldg(ppb1 + n + 1);
        int r0 = wm * 16 + (lane >> 2);
        #pragma unroll
        for (int h = 0; h < 2; h++) {
            int r = r0 + h * 8;
            stage[r * 132 + n]     = fmaxf(acc[st][h * 2 + 0] + b0, 0.f);
            stage[r * 132 + n + 1] = fmaxf(acc[st][h * 2 + 1] + b1, 0.f);
        }
    }
    __syncthreads();
    if (tid < 96) {
        int m = tid / 3, n = tid - (tid / 3) * 3;
        const float* aa = stage + m * 132;
        float s = __ldg(ppb2 + n);
        #pragma unroll 16
        for (int k = 0; k < 128; k++) s += aa[k] * __ldg(ppW2 + k * 3 + n);
        out[(size_t)(m0 + m) * 3 + n] = s;
    }
}

// ---------------- launch ----------------
extern "C" void kernel_launch(void* const* d_in, const int* in_sizes, int n_in,
                              void* d_out, int out_size)
{
    const float* x    = (const float*)d_in[0];
    const float* Rr   = (const float*)d_in[1];
    const float* Rs   = (const float*)d_in[2];
    const float* neW0 = (const float*)d_in[4];  const float* neb0 = (const float*)d_in[5];
    const float* neW1 = (const float*)d_in[6];  const float* neb1 = (const float*)d_in[7];
    const float* neW2 = (const float*)d_in[8];  const float* neb2 = (const float*)d_in[9];
    const float* eeW0 = (const float*)d_in[10]; const float* eeb0 = (const float*)d_in[11];
    const float* eeW1 = (const float*)d_in[12]; const float* eeb1 = (const float*)d_in[13];
    const float* eeW2 = (const float*)d_in[14]; const float* eeb2 = (const float*)d_in[15];
    const float* npW  = (const float*)d_in[16]; const float* npb  = (const float*)d_in[17];
    const float* epW  = (const float*)d_in[18]; const float* epb  = (const float*)d_in[19];
    const float* ppW0 = (const float*)d_in[20]; const float* ppb0 = (const float*)d_in[21];
    const float* ppW1 = (const float*)d_in[22]; const float* ppb1 = (const float*)d_in[23];
    const float* ppW2 = (const float*)d_in[24]; const float* ppb2 = (const float*)d_in[25];
    float* out = (float*)d_out;

    uint32_t* arena; cudaGetSymbolAddress((void**)&arena, g_arena);
    int* recv; cudaGetSymbolAddress((void**)&recv, g_recv);
    int* send; cudaGetSymbolAddress((void**)&send, g_send);
    __nv_bfloat16* whi; cudaGetSymbolAddress((void**)&whi, g_whi);
    __nv_bfloat16* wlo; cudaGetSymbolAddress((void**)&wlo, g_wlo);

    uint32_t* neb    = arena + OFF_NEB;
    float*    nef    = (float*)(arena + OFF_NEF);
    float*    nf1f   = (float*)(arena + OFF_NF1F);
    float*    pc     = (float*)(arena + OFF_PC);
    float*    agg0   = (float*)(arena + OFF_AGG0);
    float*    agg1   = (float*)(arena + OFF_AGG1);
    float*    prs    = (float*)(arena + OFF_PRS);
    float*    prpspA = (float*)(arena + OFF_PRPSPA);
    float*    prpspB = (float*)(arena + OFF_PRPSPB);
    float*    ec     = (float*)(arena + OFF_EC);

    const int WO[12] = {0,8192,24576,40960,57344,73728,90112,106496,139264,172032,188416,204800};

    static bool s_init = false;
    static cudaStream_t s1, s2;
    static cudaEvent_t evStart, evPrep, evS1, evNE;
    if (!s_init) {
        cudaStreamCreateWithFlags(&s1, cudaStreamNonBlocking);
        cudaStreamCreateWithFlags(&s2, cudaStreamNonBlocking);
        cudaEventCreateWithFlags(&evStart, cudaEventDisableTiming);
        cudaEventCreateWithFlags(&evPrep,  cudaEventDisableTiming);
        cudaEventCreateWithFlags(&evS1,    cudaEventDisableTiming);
        cudaEventCreateWithFlags(&evNE,    cudaEventDisableTiming);
        cudaFuncSetAttribute(node_mega,       cudaFuncAttributeMaxDynamicSharedMemorySize, NM_SMEM);
        cudaFuncSetAttribute(edge_mega,       cudaFuncAttributeMaxDynamicSharedMemorySize, EM_SMEM);
        cudaFuncSetAttribute(np_prpsp_kernel, cudaFuncAttributeMaxDynamicSharedMemorySize, NT_SMEM);
        cudaFuncSetAttribute(tail_kernel,     cudaFuncAttributeMaxDynamicSharedMemorySize, NT_SMEM);
        s_init = true;
    }

    // fork at root: extract + agg zeros on s1
    cudaEventRecord(evStart, 0);
    cudaStreamWaitEvent(s1, evStart, 0);
    extract_idx2_kernel<<<2 * BE / 8, 256, 0, s1>>>(Rr, Rs, recv, send);
    cudaMemsetAsync(agg0, 0, (size_t)2 * BN * 128 * sizeof(float), s1);
    cudaEventRecord(evS1, s1);

    // origin: weight prep
    PArg pa;
    pa.W[0] = neW0; pa.W[1] = neW1; pa.W[2] = neW2;
    pa.W[3] = eeW0; pa.W[4] = eeW1; pa.W[5] = eeW2;
    pa.W[6] = epW;  pa.W[7] = epW;  pa.W[8] = npW;
    pa.W[9] = ppW0; pa.W[10] = ppW0; pa.W[11] = ppW1;
    prep_weights<<<dim3(12, 8), 256>>>(pa, whi, wlo);
    cudaEventRecord(evPrep, 0);
    cudaStreamWaitEvent(s2, evPrep, 0);

    // s2: fused node mega-chain (PrPs + encoder + projections + pc), 512 threads
    {
        NodeArg na;
        na.x = x;
        na.eerh = whi + WO[3];        na.eerl = wlo + WO[3];
        na.eesh = whi + WO[3] + 8192; na.eesl = wlo + WO[3] + 8192;
        na.w0h = whi + WO[0]; na.w0l = wlo + WO[0];
        na.w1h = whi + WO[1]; na.w1l = wlo + WO[1];
        na.w2h = whi + WO[2]; na.w2l = wlo + WO[2];
        na.eprh = whi + WO[7];          na.eprl = wlo + WO[7];
        na.epsh = whi + WO[7] + 16384;  na.epsl = wlo + WO[7] + 16384;
        na.pqh = whi + WO[9];  na.pql = wlo + WO[9];
        na.b0 = neb0; na.b1 = neb1; na.b2 = neb2;
        na.neb = neb; na.nef = nef; na.prs = prs; na.prpsp = prpspA; na.pc = pc;
        node_mega<<<BN / 32, 512, NM_SMEM, s2>>>(na);
    }
    cudaEventRecord(evNE, s2);

    // join: indices + node outputs
    cudaStreamWaitEvent(0, evS1, 0);
    cudaStreamWaitEvent(0, evNE, 0);

    // fused edge chain + step-0 scatter (128-row tiles, vector red)
    {
        EdgeArg ea;
        ea.prs = prs; ea.recv = recv; ea.send = send; ea.eeb0 = eeb0;
        ea.w1h = whi + WO[4]; ea.w1l = wlo + WO[4];
        ea.w2h = whi + WO[5]; ea.w2l = wlo + WO[5];
        ea.weh = whi + WO[6]; ea.wel = wlo + WO[6];
        ea.b1 = eeb1; ea.b2 = eeb2;
        ea.prpsp = prpspA; ea.epb = epb;
        ea.ec = ec; ea.agg = agg0;
        edge_mega<<<BE / 128, 512, EM_SMEM>>>(ea);
    }

    // fused np(step0) + prpsp(step1), pipelined weights
    np_prpsp_kernel<<<BN / 32, 512, NT_SMEM>>>(neb, agg0, nef,
        whi + WO[8], wlo + WO[8], npb, whi + WO[7], wlo + WO[7],
        nf1f, prpspB);

    // step-1 scatter (vectorized, v4 reductions)
    fused_scatter_kernel<<<BE * 32 / 256, 256>>>(ec, prpspB, recv, send, epb, agg1);

    // fused np(step1) + predictor + output, pipelined weights
    tail_kernel<<<BN / 32, 512, NT_SMEM>>>(neb, agg1, nf1f,
        whi + WO[8], wlo + WO[8], npb, pc,
        whi + WO[10], wlo + WO[10], ppb0,
        whi + WO[11], wlo + WO[11], ppb1,
        ppW2, ppb2, out);
}

// round 16
// speedup vs baseline: 1.0135x; 1.0135x over previous
#include <cuda_runtime.h>
#include <cuda_bf16.h>
#include <cstdint>

// ---------------- problem dims ----------------
#define Nn 1024
#define Ee 8192
#define BN 4096    // B*N
#define BE 32768   // B*E

// ---------------- device scratch ----------------
#define OFF_NEB    ((size_t)0)                       // node_enc bfp
#define OFF_NEF    (OFF_NEB + (size_t)BN*128)        // node_enc f32
#define OFF_NF1F   (OFF_NEF + (size_t)BN*128)        // nf1 f32
#define OFF_PC     (OFF_NF1F + (size_t)BN*128)       // neb@pp0a f32
#define OFF_AGG0   (OFF_PC + (size_t)BN*128)
#define OFF_AGG1   (OFF_AGG0 + (size_t)BN*128)       // adjacent to agg0
#define OFF_PRS    (OFF_AGG1 + (size_t)BN*128)       // [BN,256] f32 (x@Wr | x@Ws)
#define OFF_PRPSPA (OFF_PRS + (size_t)BN*256)        // [BN,256] f32 step0
#define OFF_PRPSPB (OFF_PRPSPA + (size_t)BN*256)     // [BN,256] f32 step1
#define OFF_EC     (OFF_PRPSPB + (size_t)BN*256)     // [BE,128] f32
#define ARENA_U32  (OFF_EC + (size_t)BE*128)

__device__ uint32_t g_arena[ARENA_U32];
__device__ int g_recv[BE];
__device__ int g_send[BE];
__device__ float g_zero[256];

// split/transposed weights [n][kpad] bf16, 12 matrices
#define WT_TOTAL 221184
__device__ __nv_bfloat16 g_whi[WT_TOTAL];
__device__ __nv_bfloat16 g_wlo[WT_TOTAL];

// ---------------- helpers ----------------
__device__ __forceinline__ uint32_t smem_u32(const void* p) {
    uint32_t a;
    asm("{ .reg .u64 t; cvta.to.shared.u64 t, %1; cvt.u32.u64 %0, t; }" : "=r"(a) : "l"(p));
    return a;
}

#define LDMX4(r, ad) \
    asm volatile("ldmatrix.sync.aligned.m8n8.x4.shared.b16 {%0,%1,%2,%3}, [%4];" \
        : "=r"((r)[0]), "=r"((r)[1]), "=r"((r)[2]), "=r"((r)[3]) : "r"(ad))

#define MMA16816(d, av, bv) \
    asm volatile("mma.sync.aligned.m16n8k16.row.col.f32.bf16.bf16.f32 " \
        "{%0,%1,%2,%3},{%4,%5,%6,%7},{%8,%9},{%0,%1,%2,%3};" \
        : "+f"((d)[0]), "+f"((d)[1]), "+f"((d)[2]), "+f"((d)[3]) \
        : "r"((av)[0]), "r"((av)[1]), "r"((av)[2]), "r"((av)[3]), \
          "r"((bv)[0]), "r"((bv)[1]))

#define CP_ASYNC16(sa, gp) \
    asm volatile("cp.async.cg.shared.global [%0], [%1], 16;" :: "r"(sa), "l"(gp))
#define CP_COMMIT()  asm volatile("cp.async.commit_group;" ::: "memory")
#define CP_WAIT1()   asm volatile("cp.async.wait_group 1;" ::: "memory")
#define CP_WAIT0()   asm volatile("cp.async.wait_group 0;" ::: "memory")

#define REDV2(ptr, v0, v1) \
    asm volatile("red.global.add.v2.f32 [%0], {%1, %2};" \
        :: "l"(ptr), "f"(v0), "f"(v1) : "memory")
#define REDV4(ptr, v0, v1, v2, v3) \
    asm volatile("red.global.add.v4.f32 [%0], {%1, %2, %3, %4};" \
        :: "l"(ptr), "f"(v0), "f"(v1), "f"(v2), "f"(v3) : "memory")

__device__ __forceinline__ uint32_t packbfp(float v) {
    __nv_bfloat16 h = __float2bfloat16(v);
    float hf = __bfloat162float(h);
    __nv_bfloat16 l = __float2bfloat16(v - hf);
    return (uint32_t)__bfloat16_as_ushort(h) | ((uint32_t)__bfloat16_as_ushort(l) << 16);
}

// ---- 32-col-warp 3-pass MMA (node_mega, 256 threads) ----
__device__ __forceinline__ void mma_span1(
    uint32_t aHi, uint32_t aLo, uint32_t bHi, uint32_t bLo,
    int astr, int bstr, int nk, float (*acc)[4], int tile, int wn, int lane)
{
    for (int ks = 0; ks < nk; ks++) {
        uint32_t bh[8], bl[8];
        #pragma unroll
        for (int np = 0; np < 2; np++) {
            int n = wn * 32 + np * 16 + ((lane >> 4) << 3) + (lane & 7);
            int koff = ((lane >> 3) & 1) << 3;
            uint32_t ad = bHi + n * bstr + (ks * 16 + koff) * 2;
            LDMX4(&bh[np * 4], ad);
            LDMX4(&bl[np * 4], ad + (bLo - bHi));
        }
        int r = tile * 16 + (lane & 15);
        int koff = (lane >> 4) << 3;
        uint32_t ad = aHi + r * astr + (ks * 16 + koff) * 2;
        uint32_t ah[4], al[4];
        LDMX4(ah, ad);
        LDMX4(al, ad + (aLo - aHi));
        #pragma unroll
        for (int st = 0; st < 4; st++) {
            MMA16816(acc[st], ah, &bh[st * 2]);
            MMA16816(acc[st], ah, &bl[st * 2]);
            MMA16816(acc[st], al, &bh[st * 2]);
        }
    }
}

// ---- 32-col-warp, 4 m-tiles per warp (edge_mega, 256 threads) ----
__device__ __forceinline__ void mma_span_mt4(
    uint32_t aHi, uint32_t aLo, uint32_t bHi, uint32_t bLo,
    int astr, int bstr, int nk, float acc[4][4][4],
    int tile0, int wn, int lane)
{
    for (int ks = 0; ks < nk; ks++) {
        uint32_t bh[8], bl[8];
        #pragma unroll
        for (int np = 0; np < 2; np++) {
            int n = wn * 32 + np * 16 + ((lane >> 4) << 3) + (lane & 7);
            int koff = ((lane >> 3) & 1) << 3;
            uint32_t ad = bHi + n * bstr + (ks * 16 + koff) * 2;
            LDMX4(&bh[np * 4], ad);
            LDMX4(&bl[np * 4], ad + (bLo - bHi));
        }
        int koff = (lane >> 4) << 3;
        uint32_t ah[4][4], al[4][4];
        #pragma unroll
        for (int mt = 0; mt < 4; mt++) {
            int r = (tile0 + mt) * 16 + (lane & 15);
            uint32_t ad = aHi + r * astr + (ks * 16 + koff) * 2;
            LDMX4(ah[mt], ad);
            LDMX4(al[mt], ad + (aLo - aHi));
        }
        #pragma unroll
        for (int st = 0; st < 4; st++)
            #pragma unroll
            for (int mt = 0; mt < 4; mt++) {
                MMA16816(acc[mt][st], ah[mt], &bh[st * 2]);
                MMA16816(acc[mt][st], ah[mt], &bl[st * 2]);
                MMA16816(acc[mt][st], al[mt], &bh[st * 2]);
            }
    }
}

// ---- 16-col-warp 3-pass MMA (np/tail kernels, 512 threads): wn in 0..7 ----
__device__ __forceinline__ void mma_span16(
    uint32_t aHi, uint32_t aLo, uint32_t bHi, uint32_t bLo,
    int astr, int bstr, int nk, float (*acc)[4], int tile, int wn, int lane)
{
    for (int ks = 0; ks < nk; ks++) {
        uint32_t bh[4], bl[4];
        int n = wn * 16 + ((lane >> 4) << 3) + (lane & 7);
        int koff = ((lane >> 3) & 1) << 3;
        uint32_t ad = bHi + n * bstr + (ks * 16 + koff) * 2;
        LDMX4(bh, ad);
        LDMX4(bl, ad + (bLo - bHi));
        int r = tile * 16 + (lane & 15);
        int koff2 = (lane >> 4) << 3;
        uint32_t ad2 = aHi + r * astr + (ks * 16 + koff2) * 2;
        uint32_t ah[4], al[4];
        LDMX4(ah, ad2);
        LDMX4(al, ad2 + (aLo - aHi));
        #pragma unroll
        for (int st = 0; st < 2; st++) {
            MMA16816(acc[st], ah, &bh[st * 2]);
            MMA16816(acc[st], ah, &bl[st * 2]);
            MMA16816(acc[st], al, &bh[st * 2]);
        }
    }
}

// async weight load with K-window (cp.async, caller commits/waits)
__device__ __forceinline__ void load_Bw_cp(uint32_t sbase, int plane,
    const __nv_bfloat16* Bhi, const __nv_bfloat16* Blo,
    int nrows, int kwin, int fullK, int k0, int bstr, int tid, int nth)
{
    int kg = kwin >> 3;
    int per = nrows * kg;
    for (int item = tid; item < per; item += nth) {
        int n = item / kg, g = item - n * kg;
        size_t goff = (size_t)n * fullK + k0 + (g << 3);
        uint32_t so = sbase + n * bstr + (g << 4);
        CP_ASYNC16(so, Bhi + goff);
        CP_ASYNC16(so + plane, Blo + goff);
    }
}

// 32-col-warp epilogue, full-featured (node_mega)
__device__ __forceinline__ void epi_repack2(char* smem, int astr, int aplane,
    float (*acc)[4], int m0, int tile,
    const float* bias, const float* resid, float* outf, uint32_t* outb,
    int wn, int lane)
{
    #pragma unroll
    for (int st = 0; st < 4; st++) {
        int n = wn * 32 + st * 8 + ((lane & 3) << 1);
        float b0 = __ldg(bias + n), b1 = __ldg(bias + n + 1);
        int r0 = tile * 16 + (lane >> 2);
        #pragma unroll
        for (int h = 0; h < 2; h++) {
            int r = r0 + h * 8;
            float s0 = acc[st][h * 2 + 0] + b0;
            float s1 = acc[st][h * 2 + 1] + b1;
            if (resid) {
                float2 rv = *(const float2*)(resid + (((size_t)(m0 + r)) << 7) + n);
                s0 += rv.x; s1 += rv.y;
            }
            s0 = fmaxf(s0, 0.f); s1 = fmaxf(s1, 0.f);
            if (outf) *(float2*)(outf + (((size_t)(m0 + r)) << 7) + n) = make_float2(s0, s1);
            uint32_t p0 = packbfp(s0), p1 = packbfp(s1);
            if (outb) *(uint2*)(outb + (((size_t)(m0 + r)) << 7) + n) = make_uint2(p0, p1);
            int off = r * astr + n * 2;
            *(uint32_t*)(smem + off) = (p0 & 0xffffu) | (p1 << 16);
            *(uint32_t*)(smem + aplane + off) = (p0 >> 16) | (p1 & 0xffff0000u);
            acc[st][h * 2 + 0] = 0.f;
            acc[st][h * 2 + 1] = 0.f;
        }
    }
}

// 32-col-warp epilogue, bias-only (edge_mega)
__device__ __forceinline__ void epi_repack2e(char* smem, int astr, int aplane,
    float (*acc)[4], int tile, const float* bias, int wn, int lane)
{
    #pragma unroll
    for (int st = 0; st < 4; st++) {
        int n = wn * 32 + st * 8 + ((lane & 3) << 1);
        float b0 = __ldg(bias + n), b1 = __ldg(bias + n + 1);
        int r0 = tile * 16 + (lane >> 2);
        #pragma unroll
        for (int h = 0; h < 2; h++) {
            int r = r0 + h * 8;
            float s0 = fmaxf(acc[st][h * 2 + 0] + b0, 0.f);
            float s1 = fmaxf(acc[st][h * 2 + 1] + b1, 0.f);
            uint32_t p0 = packbfp(s0), p1 = packbfp(s1);
            int off = r * astr + n * 2;
            *(uint32_t*)(smem + off) = (p0 & 0xffffu) | (p1 << 16);
            *(uint32_t*)(smem + aplane + off) = (p0 >> 16) | (p1 & 0xffff0000u);
            acc[st][h * 2 + 0] = 0.f;
            acc[st][h * 2 + 1] = 0.f;
        }
    }
}

// 16-col-warp epilogue
__device__ __forceinline__ void epi_repack16(char* smem, int astr, int aplane,
    float (*acc)[4], int m0, int tile,
    const float* bias, const float* resid, float* outf,
    int wn, int lane)
{
    #pragma unroll
    for (int st = 0; st < 2; st++) {
        int n = wn * 16 + st * 8 + ((lane & 3) << 1);
        float b0 = __ldg(bias + n), b1 = __ldg(bias + n + 1);
        int r0 = tile * 16 + (lane >> 2);
        #pragma unroll
        for (int h = 0; h < 2; h++) {
            int r = r0 + h * 8;
            float s0 = acc[st][h * 2 + 0] + b0;
            float s1 = acc[st][h * 2 + 1] + b1;
            if (resid) {
                float2 rv = *(const float2*)(resid + (((size_t)(m0 + r)) << 7) + n);
                s0 += rv.x; s1 += rv.y;
            }
            s0 = fmaxf(s0, 0.f); s1 = fmaxf(s1, 0.f);
            if (outf) *(float2*)(outf + (((size_t)(m0 + r)) << 7) + n) = make_float2(s0, s1);
            uint32_t p0 = packbfp(s0), p1 = packbfp(s1);
            int off = r * astr + n * 2;
            *(uint32_t*)(smem + off) = (p0 & 0xffffu) | (p1 << 16);
            *(uint32_t*)(smem + aplane + off) = (p0 >> 16) | (p1 & 0xffff0000u);
            acc[st][h * 2 + 0] = 0.f;
            acc[st][h * 2 + 1] = 0.f;
        }
    }
}

// write acc f32 (32-col warps)
__device__ __forceinline__ void write_accf(float (*acc)[4], int m0, int tile,
    int wn, int lane, float* out, int nbase, int ldo)
{
    #pragma unroll
    for (int st = 0; st < 4; st++) {
        int n = nbase + wn * 32 + st * 8 + ((lane & 3) << 1);
        int r0 = tile * 16 + (lane >> 2);
        #pragma unroll
        for (int h = 0; h < 2; h++) {
            int m = m0 + r0 + h * 8;
            *(float2*)(out + (size_t)m * ldo + n) =
                make_float2(acc[st][h * 2 + 0], acc[st][h * 2 + 1]);
            acc[st][h * 2 + 0] = 0.f;
            acc[st][h * 2 + 1] = 0.f;
        }
    }
}

// write acc f32 (16-col warps)
__device__ __forceinline__ void write_accf16(float (*acc)[4], int m0, int tile,
    int wn, int lane, float* out, int nbase, int ldo)
{
    #pragma unroll
    for (int st = 0; st < 2; st++) {
        int n = nbase + wn * 16 + st * 8 + ((lane & 3) << 1);
        int r0 = tile * 16 + (lane >> 2);
        #pragma unroll
        for (int h = 0; h < 2; h++) {
            int m = m0 + r0 + h * 8;
            *(float2*)(out + (size_t)m * ldo + n) =
                make_float2(acc[st][h * 2 + 0], acc[st][h * 2 + 1]);
            acc[st][h * 2 + 0] = 0.f;
            acc[st][h * 2 + 1] = 0.f;
        }
    }
}

// ---------------- aux kernels ----------------
__global__ void extract_idx2_kernel(const float* __restrict__ Rr,
                                    const float* __restrict__ Rs,
                                    int* __restrict__ recv, int* __restrict__ send)
{
    int row = blockIdx.x * 8 + (threadIdx.x >> 5);
    int lane = threadIdx.x & 31;
    const float* R = (row < BE) ? Rr : Rs;
    int r = (row < BE) ? row : row - BE;
    const float4* p = (const float4*)(R + (size_t)r * Nn);
    int found = -1;
    #pragma unroll
    for (int i = 0; i < 4; i++) {
        int q = lane + i * 32;
        float4 v = p[q];
        if (v.x > 0.5f) found = q * 4 + 0;
        if (v.y > 0.5f) found = q * 4 + 1;
        if (v.z > 0.5f) found = q * 4 + 2;
        if (v.w > 0.5f) found = q * 4 + 3;
    }
    if (__ballot_sync(0xFFFFFFFFu, found >= 0) == 0u) {
        #pragma unroll
        for (int i = 4; i < 8; i++) {
            int q = lane + i * 32;
            float4 v = p[q];
            if (v.x > 0.5f) found = q * 4 + 0;
            if (v.y > 0.5f) found = q * 4 + 1;
            if (v.z > 0.5f) found = q * 4 + 2;
            if (v.w > 0.5f) found = q * 4 + 3;
        }
    }
    #pragma unroll
    for (int o = 16; o; o >>= 1) found = max(found, __shfl_xor_sync(0xFFFFFFFFu, found, o));
    if (lane == 0) {
        found = max(found, 0);
        if (row < BE) recv[r] = found; else send[r] = found;
    }
}

// matrices: 0 ne0 1 ne1 2 ne2 3 eers(R256) 4 ee1 5 ee2 6 ep_e 7 ep_rs(R256)
//           8 np(K256) 9 pp0a 10 pp0b 11 pp1
struct PArg { const float* W[12]; };
__constant__ int c_Ks[12]  = {32,128,128, 32,128,128,128,128,256,128,128,128};
__constant__ int c_Kps[12] = {64,128,128, 64,128,128,128,128,256,128,128,128};
__constant__ int c_Rs[12]  = {128,128,128,256,128,128,128,256,128,128,128,128};
__constant__ int c_r0a[12] = {0,0,0,0,0,0,0,128,0,0,128,0};
__constant__ int c_r0b[12] = {0,0,0,32,0,0,0,256,0,0,0,0};
__constant__ int c_off[12] = {0,8192,24576,40960,57344,73728,90112,106496,139264,172032,188416,204800};

__global__ void prep_weights(PArg a, __nv_bfloat16* __restrict__ hi, __nv_bfloat16* __restrict__ lo)
{
    int mid = blockIdx.x;
    int K = c_Ks[mid], Kp = c_Kps[mid], R = c_Rs[mid];
    int r0a = c_r0a[mid], r0b = c_r0b[mid];
    const float* W = a.W[mid];
    __nv_bfloat16* dh = hi + c_off[mid];
    __nv_bfloat16* dl = lo + c_off[mid];
    int total = R * Kp;
    for (int i = threadIdx.x + blockIdx.y * blockDim.x; i < total; i += blockDim.x * gridDim.y) {
        int n = i / Kp, k = i - n * Kp;
        int col = n & 127;
        int r0 = (n >> 7) ? r0b : r0a;
        float v = (k < K) ? W[(size_t)(r0 + k) * 128 + col] : 0.f;
        __nv_bfloat16 h = __float2bfloat16(v);
        dh[i] = h;
        dl[i] = __float2bfloat16(v - __bfloat162float(h));
    }
}

// step-1 scatter: 4 h-values per thread, vector reduction
__global__ void fused_scatter_kernel(const float* __restrict__ ec,
                                     const float* __restrict__ prpsp,
                                     const int* __restrict__ recv,
                                     const int* __restrict__ send,
                                     const float* __restrict__ bias,
                                     float* __restrict__ agg)
{
    int t = blockIdx.x * blockDim.x + threadIdx.x;   // BE*32
    if (t >= BE * 32) return;
    int e = t >> 5, q = t & 31;
    int h = q << 2;
    int bo = (e >> 13) << 10;
    int r = __ldg(recv + e) + bo, s = __ldg(send + e) + bo;
    float4 ev = *(const float4*)(ec + ((size_t)e << 7) + h);
    float4 pr = *(const float4*)(prpsp + (size_t)r * 256 + h);
    float4 ps = *(const float4*)(prpsp + (size_t)s * 256 + 128 + h);
    float4 bb = *(const float4*)(bias + h);
    float v0 = fmaxf(ev.x + pr.x + ps.x + bb.x, 0.f);
    float v1 = fmaxf(ev.y + pr.y + ps.y + bb.y, 0.f);
    float v2 = fmaxf(ev.z + pr.z + ps.z + bb.z, 0.f);
    float v3 = fmaxf(ev.w + pr.w + ps.w + bb.w, 0.f);
    REDV4(agg + (size_t)r * 128 + h, v0, v1, v2, v3);
}

// ---------------- node_mega: eer,ees,ne0..ne2,epr,eps,pc (256 thr, ping-pong) ----------------
#define NM_STR   272
#define NM_ALO   (32 * NM_STR)
#define NM_B0    (2 * NM_ALO)
#define NM_BPL   (128 * NM_STR)
#define NM_SLOT  (2 * NM_BPL)
#define NM_SMEM  (NM_B0 + 2 * NM_SLOT)     // 156672

struct NodeArg {
    const float* x;
    const __nv_bfloat16 *eerh,*eerl,*eesh,*eesl;
    const __nv_bfloat16 *w0h,*w0l,*w1h,*w1l,*w2h,*w2l,*eprh,*eprl,*epsh,*epsl,*pqh,*pql;
    const float *b0,*b1,*b2;
    uint32_t* neb; float* nef; float* prs; float* prpsp; float* pc;
};

__global__ __launch_bounds__(256) void node_mega(NodeArg a)
{
    extern __shared__ char smem[];
    const uint32_t sb = smem_u32(smem);
    const int tid = threadIdx.x;
    const int wid = tid >> 5, lane = tid & 31;
    const int wm = wid & 1, wn = wid >> 1;
    const int m0 = blockIdx.x * 32;

    const uint32_t sA = sb + NM_B0;
    const uint32_t sB = sb + NM_B0 + NM_SLOT;

    float acc[4][4];
    #pragma unroll
    for (int st = 0; st < 4; st++)
        #pragma unroll
        for (int r = 0; r < 4; r++) acc[st][r] = 0.f;

    load_Bw_cp(sA, NM_BPL, a.eerh, a.eerl, 128, 64, 64, 0, NM_STR, tid, 256); CP_COMMIT();
    load_Bw_cp(sB, NM_BPL, a.eesh, a.eesl, 128, 64, 64, 0, NM_STR, tid, 256); CP_COMMIT();

    #pragma unroll
    for (int it = 0; it < 2; it++) {
        int item = tid + (it << 8);
        int r = item >> 4, g = item & 15;
        int kc = g << 2;
        uint32_t p0 = 0, p1 = 0, p2 = 0, p3 = 0;
        if (kc < 32) {
            float4 v = *(const float4*)(a.x + (size_t)(m0 + r) * 32 + kc);
            p0 = packbfp(v.x); p1 = packbfp(v.y); p2 = packbfp(v.z); p3 = packbfp(v.w);
        }
        uint32_t hi01 = (p0 & 0xffffu) | (p1 << 16);
        uint32_t hi23 = (p2 & 0xffffu) | (p3 << 16);
        uint32_t lo01 = (p0 >> 16) | (p1 & 0xffff0000u);
        uint32_t lo23 = (p2 >> 16) | (p3 & 0xffff0000u);
        int off = r * NM_STR + g * 8;
        *(uint2*)(smem + off) = make_uint2(hi01, hi23);
        *(uint2*)(smem + NM_ALO + off) = make_uint2(lo01, lo23);
    }

    // P0: eer -> prs[:,0:128]
    CP_WAIT1(); __syncthreads();
    mma_span1(sb, sb + NM_ALO, sA, sA + NM_BPL, NM_STR, NM_STR, 4, acc, wm, wn, lane);
    __syncthreads();
    write_accf(acc, m0, wm, wn, lane, a.prs, 0, 256);
    load_Bw_cp(sA, NM_BPL, a.w0h, a.w0l, 128, 64, 64, 0, NM_STR, tid, 256); CP_COMMIT();

    // P1: ees -> prs[:,128:256]
    CP_WAIT1(); __syncthreads();
    mma_span1(sb, sb + NM_ALO, sB, sB + NM_BPL, NM_STR, NM_STR, 4, acc, wm, wn, lane);
    __syncthreads();
    write_accf(acc, m0, wm, wn, lane, a.prs, 128, 256);
    load_Bw_cp(sB, NM_BPL, a.w1h, a.w1l, 128, 128, 128, 0, NM_STR, tid, 256); CP_COMMIT();

    // P2: ne0
    CP_WAIT1(); __syncthreads();
    mma_span1(sb, sb + NM_ALO, sA, sA + NM_BPL, NM_STR, NM_STR, 4, acc, wm, wn, lane);
    __syncthreads();
    epi_repack2(smem, NM_STR, NM_ALO, acc, m0, wm, a.b0, nullptr, nullptr, nullptr, wn, lane);
    load_Bw_cp(sA, NM_BPL, a.w2h, a.w2l, 128, 128, 128, 0, NM_STR, tid, 256); CP_COMMIT();

    // P3: ne1
    CP_WAIT1(); __syncthreads();
    mma_span1(sb, sb + NM_ALO, sB, sB + NM_BPL, NM_STR, NM_STR, 8, acc, wm, wn, lane);
    __syncthreads();
    epi_repack2(smem, NM_STR, NM_ALO, acc, m0, wm, a.b1, nullptr, nullptr, nullptr, wn, lane);
    load_Bw_cp(sB, NM_BPL, a.eprh, a.eprl, 128, 128, 128, 0, NM_STR, tid, 256); CP_COMMIT();

    // P4: ne2 -> neb/nef
    CP_WAIT1(); __syncthreads();
    mma_span1(sb, sb + NM_ALO, sA, sA + NM_BPL, NM_STR, NM_STR, 8, acc, wm, wn, lane);
    __syncthreads();
    epi_repack2(smem, NM_STR, NM_ALO, acc, m0, wm, a.b2, nullptr, a.nef, a.neb, wn, lane);
    load_Bw_cp(sA, NM_BPL, a.epsh, a.epsl, 128, 128, 128, 0, NM_STR, tid, 256); CP_COMMIT();

    // P5: epr -> prpspA[:,0:128]
    CP_WAIT1(); __syncthreads();
    mma_span1(sb, sb + NM_ALO, sB, sB + NM_BPL, NM_STR, NM_STR, 8, acc, wm, wn, lane);
    __syncthreads();
    write_accf(acc, m0, wm, wn, lane, a.prpsp, 0, 256);
    load_Bw_cp(sB, NM_BPL, a.pqh, a.pql, 128, 128, 128, 0, NM_STR, tid, 256); CP_COMMIT();

    // P6: eps -> prpspA[:,128:256]
    CP_WAIT1(); __syncthreads();
    mma_span1(sb, sb + NM_ALO, sA, sA + NM_BPL, NM_STR, NM_STR, 8, acc, wm, wn, lane);
    __syncthreads();
    write_accf(acc, m0, wm, wn, lane, a.prpsp, 128, 256);

    // P7: pc
    CP_WAIT0(); __syncthreads();
    mma_span1(sb, sb + NM_ALO, sB, sB + NM_BPL, NM_STR, NM_STR, 8, acc, wm, wn, lane);
    __syncthreads();
    write_accf(acc, m0, wm, wn, lane, a.pc, 0, 128);
}

// ---------------- edge_mega: 128-row tiles, 256 thr, 2m x 4n warps (mt=4) ----------------
#define EM_STR   272
#define EM_APL   (128 * EM_STR)
#define EM_B0    (2 * EM_APL)
#define EM_BPL   (128 * EM_STR)
#define EM_SLOT  (2 * EM_BPL)
#define EM_SMEM  (EM_B0 + 2 * EM_SLOT)     // 208896

struct EdgeArg {
    const float* prs; const int* recv; const int* send; const float* eeb0;
    const __nv_bfloat16 *w1h,*w1l,*w2h,*w2l,*weh,*wel;
    const float *b1,*b2;
    const float* prpsp; const float* epb;
    float* ec; float* agg;
};

__global__ __launch_bounds__(256, 1) void edge_mega(EdgeArg a)
{
    extern __shared__ char smem[];
    const uint32_t sb = smem_u32(smem);
    const int tid = threadIdx.x;
    const int wid = tid >> 5, lane = tid & 31;
    const int wm = wid & 1, wn = wid >> 1;      // 2m x 4n warp grid; 64 rows x 32 cols per warp
    const int m0 = blockIdx.x * 128;

    const uint32_t sA = sb + EM_B0;
    const uint32_t sB = sb + EM_B0 + EM_SLOT;

    float acc[4][4][4];
    #pragma unroll
    for (int mt = 0; mt < 4; mt++)
        #pragma unroll
        for (int st = 0; st < 4; st++)
            #pragma unroll
            for (int r = 0; r < 4; r++) acc[mt][st][r] = 0.f;

    load_Bw_cp(sA, EM_BPL, a.w1h, a.w1l, 128, 128, 128, 0, EM_STR, tid, 256); CP_COMMIT();
    load_Bw_cp(sB, EM_BPL, a.w2h, a.w2l, 128, 128, 128, 0, EM_STR, tid, 256); CP_COMMIT();

    // A <- edge layer0 on the fly: relu(Pr[recv]+Ps[send]+b0), 128 rows x 128 cols
    #pragma unroll
    for (int it = 0; it < 16; it++) {
        int item = tid + (it << 8);
        int r = item >> 5, g = item & 31;
        int kc = g << 2;
        int m = m0 + r;
        int bo = (m >> 13) << 10;
        int rr = __ldg(a.recv + m) + bo, ss = __ldg(a.send + m) + bo;
        float4 pr = *(const float4*)(a.prs + (size_t)rr * 256 + kc);
        float4 ps = *(const float4*)(a.prs + (size_t)ss * 256 + 128 + kc);
        float4 bb = *(const float4*)(a.eeb0 + kc);
        uint32_t p0 = packbfp(fmaxf(pr.x + ps.x + bb.x, 0.f));
        uint32_t p1 = packbfp(fmaxf(pr.y + ps.y + bb.y, 0.f));
        uint32_t p2 = packbfp(fmaxf(pr.z + ps.z + bb.z, 0.f));
        uint32_t p3 = packbfp(fmaxf(pr.w + ps.w + bb.w, 0.f));
        uint32_t hi01 = (p0 & 0xffffu) | (p1 << 16);
        uint32_t hi23 = (p2 & 0xffffu) | (p3 << 16);
        uint32_t lo01 = (p0 >> 16) | (p1 & 0xffff0000u);
        uint32_t lo23 = (p2 >> 16) | (p3 & 0xffff0000u);
        int off = r * EM_STR + g * 8;
        *(uint2*)(smem + off) = make_uint2(hi01, hi23);
        *(uint2*)(smem + EM_APL + off) = make_uint2(lo01, lo23);
    }

    // phase 1: ee1 (sA)
    CP_WAIT1(); __syncthreads();
    mma_span_mt4(sb, sb + EM_APL, sA, sA + EM_BPL, EM_STR, EM_STR, 8,
                 acc, wm * 4, wn, lane);
    __syncthreads();
    #pragma unroll
    for (int mt = 0; mt < 4; mt++)
        epi_repack2e(smem, EM_STR, EM_APL, acc[mt], wm * 4 + mt, a.b1, wn, lane);
    load_Bw_cp(sA, EM_BPL, a.weh, a.wel, 128, 128, 128, 0, EM_STR, tid, 256); CP_COMMIT();

    // phase 2: ee2 (sB)
    CP_WAIT1(); __syncthreads();
    mma_span_mt4(sb, sb + EM_APL, sB, sB + EM_BPL, EM_STR, EM_STR, 8,
                 acc, wm * 4, wn, lane);
    __syncthreads();
    #pragma unroll
    for (int mt = 0; mt < 4; mt++)
        epi_repack2e(smem, EM_STR, EM_APL, acc[mt], wm * 4 + mt, a.b2, wn, lane);

    // phase 3: ec (sA)
    CP_WAIT0(); __syncthreads();
    mma_span_mt4(sb, sb + EM_APL, sA, sA + EM_BPL, EM_STR, EM_STR, 8,
                 acc, wm * 4, wn, lane);

    // epilogue: write ec + fused step-0 scatter (vector reductions)
    #pragma unroll
    for (int mt = 0; mt < 4; mt++) {
        int row0 = m0 + (wm * 4 + mt) * 16 + (lane >> 2);
        #pragma unroll
        for (int st = 0; st < 4; st++) {
            int n = wn * 32 + st * 8 + ((lane & 3) << 1);
            float e0b = __ldg(a.epb + n), e1b = __ldg(a.epb + n + 1);
            #pragma unroll
            for (int h = 0; h < 2; h++) {
                int m = row0 + h * 8;
                float e0 = acc[mt][st][h * 2 + 0];
                float e1 = acc[mt][st][h * 2 + 1];
                *(float2*)(a.ec + ((size_t)m << 7) + n) = make_float2(e0, e1);
                int bo = (m >> 13) << 10;
                int r_ = __ldg(a.recv + m) + bo, s_ = __ldg(a.send + m) + bo;
                float2 pr = *(const float2*)(a.prpsp + (size_t)r_ * 256 + n);
                float2 ps = *(const float2*)(a.prpsp + (size_t)s_ * 256 + 128 + n);
                float v0 = fmaxf(e0 + pr.x + ps.x + e0b, 0.f);
                float v1 = fmaxf(e1 + pr.y + ps.y + e1b, 0.f);
                REDV2(a.agg + (size_t)r_ * 128 + n, v0, v1);
            }
        }
    }
}

// ---------------- np_prpsp / tail (512 threads, ping-pong, K-chunked np) ----------------
#define NSTR   528
#define N_ALO  (32 * NSTR)
#define N_B0   (2 * N_ALO)
#define N_BPL  (128 * 272)
#define N_SLOT (2 * N_BPL)
#define NT_SMEM (N_B0 + 2 * N_SLOT)        // 173056

__device__ __forceinline__ void load_A_npagg(char* smem, int m0,
    const uint32_t* neb, const float* agg, int tid)
{
    #pragma unroll
    for (int it = 0; it < 4; it++) {
        int item = tid + (it << 9);
        int r = item >> 6, g = item & 63;
        int kc = g << 2;
        int m = m0 + r;
        uint32_t p0, p1, p2, p3;
        if (kc < 128) {
            uint4 v = *(const uint4*)(neb + ((size_t)m << 7) + kc);
            p0 = v.x; p1 = v.y; p2 = v.z; p3 = v.w;
        } else {
            float4 v = *(const float4*)(agg + ((size_t)m << 7) + (kc - 128));
            p0 = packbfp(v.x); p1 = packbfp(v.y); p2 = packbfp(v.z); p3 = packbfp(v.w);
        }
        uint32_t hi01 = (p0 & 0xffffu) | (p1 << 16);
        uint32_t hi23 = (p2 & 0xffffu) | (p3 << 16);
        uint32_t lo01 = (p0 >> 16) | (p1 & 0xffff0000u);
        uint32_t lo23 = (p2 >> 16) | (p3 & 0xffff0000u);
        int off = r * NSTR + g * 8;
        *(uint2*)(smem + off) = make_uint2(hi01, hi23);
        *(uint2*)(smem + N_ALO + off) = make_uint2(lo01, lo23);
    }
}

__global__ __launch_bounds__(512, 1) void np_prpsp_kernel(
    const uint32_t* __restrict__ neb, const float* __restrict__ agg,
    const float* __restrict__ resid,
    const __nv_bfloat16* __restrict__ npHi, const __nv_bfloat16* __restrict__ npLo,
    const float* __restrict__ npb,
    const __nv_bfloat16* __restrict__ epHi, const __nv_bfloat16* __restrict__ epLo,
    float* __restrict__ nf_out, float* __restrict__ prpsp_out)
{
    extern __shared__ char smem[];
    const uint32_t sb = smem_u32(smem);
    const int tid = threadIdx.x;
    const int wid = tid >> 5, lane = tid & 31;
    const int wm = wid & 1, wn = wid >> 1;
    const int m0 = blockIdx.x * 32;

    const uint32_t sA = sb + N_B0;
    const uint32_t sB = sb + N_B0 + N_SLOT;

    float acc[2][4];
    #pragma unroll
    for (int st = 0; st < 2; st++)
        #pragma unroll
        for (int r = 0; r < 4; r++) acc[st][r] = 0.f;

    load_Bw_cp(sA, N_BPL, npHi, npLo, 128, 128, 256, 0,   272, tid, 512); CP_COMMIT();
    load_Bw_cp(sB, N_BPL, npHi, npLo, 128, 128, 256, 128, 272, tid, 512); CP_COMMIT();

    load_A_npagg(smem, m0, neb, agg, tid);

    CP_WAIT1(); __syncthreads();
    mma_span16(sb, sb + N_ALO, sA, sA + N_BPL, NSTR, 272, 8, acc, wm, wn, lane);
    __syncthreads();
    load_Bw_cp(sA, N_BPL, epHi, epLo, 128, 128, 128, 0, 272, tid, 512); CP_COMMIT();
    CP_WAIT1(); __syncthreads();
    mma_span16(sb + 256, sb + N_ALO + 256, sB, sB + N_BPL, NSTR, 272, 8, acc, wm, wn, lane);
    __syncthreads();
    epi_repack16(smem, NSTR, N_ALO, acc, m0, wm, npb, resid, nf_out, wn, lane);
    load_Bw_cp(sB, N_BPL, epHi + 128 * 128, epLo + 128 * 128, 128, 128, 128, 0, 272, tid, 512); CP_COMMIT();

    CP_WAIT1(); __syncthreads();
    mma_span16(sb, sb + N_ALO, sA, sA + N_BPL, NSTR, 272, 8, acc, wm, wn, lane);
    __syncthreads();
    write_accf16(acc, m0, wm, wn, lane, prpsp_out, 0, 256);

    CP_WAIT0(); __syncthreads();
    mma_span16(sb, sb + N_ALO, sB, sB + N_BPL, NSTR, 272, 8, acc, wm, wn, lane);
    __syncthreads();
    write_accf16(acc, m0, wm, wn, lane, prpsp_out, 128, 256);
}

__global__ __launch_bounds__(512, 1) void tail_kernel(
    const uint32_t* __restrict__ neb, const float* __restrict__ agg1,
    const float* __restrict__ nf1,
    const __nv_bfloat16* __restrict__ npHi, const __nv_bfloat16* __restrict__ npLo,
    const float* __restrict__ npb,
    const float* __restrict__ pc,
    const __nv_bfloat16* __restrict__ p0bHi, const __nv_bfloat16* __restrict__ p0bLo,
    const float* __restrict__ ppb0,
    const __nv_bfloat16* __restrict__ p1Hi, const __nv_bfloat16* __restrict__ p1Lo,
    const float* __restrict__ ppb1,
    const float* __restrict__ ppW2, const float* __restrict__ ppb2,
    float* __restrict__ out)
{
    extern __shared__ char smem[];
    const uint32_t sb = smem_u32(smem);
    const int tid = threadIdx.x;
    const int wid = tid >> 5, lane = tid & 31;
    const int wm = wid & 1, wn = wid >> 1;
    const int m0 = blockIdx.x * 32;

    const uint32_t sA = sb + N_B0;
    const uint32_t sB = sb + N_B0 + N_SLOT;

    float acc[2][4];
    #pragma unroll
    for (int st = 0; st < 2; st++)
        #pragma unroll
        for (int r = 0; r < 4; r++) acc[st][r] = 0.f;

    load_Bw_cp(sA, N_BPL, npHi, npLo, 128, 128, 256, 0,   272, tid, 512); CP_COMMIT();
    load_Bw_cp(sB, N_BPL, npHi, npLo, 128, 128, 256, 128, 272, tid, 512); CP_COMMIT();

    load_A_npagg(smem, m0, neb, agg1, tid);

    CP_WAIT1(); __syncthreads();
    mma_span16(sb, sb + N_ALO, sA, sA + N_BPL, NSTR, 272, 8, acc, wm, wn, lane);
    __syncthreads();
    load_Bw_cp(sA, N_BPL, p0bHi, p0bLo, 128, 128, 128, 0, 272, tid, 512); CP_COMMIT();
    CP_WAIT1(); __syncthreads();
    mma_span16(sb + 256, sb + N_ALO + 256, sB, sB + N_BPL, NSTR, 272, 8, acc, wm, wn, lane);
    __syncthreads();
    epi_repack16(smem, NSTR, N_ALO, acc, m0, wm, npb, nf1, nullptr, wn, lane);
    load_Bw_cp(sB, N_BPL, p1Hi, p1Lo, 128, 128, 128, 0, 272, tid, 512); CP_COMMIT();

    CP_WAIT1(); __syncthreads();
    mma_span16(sb, sb + N_ALO, sA, sA + N_BPL, NSTR, 272, 8, acc, wm, wn, lane);
    __syncthreads();
    epi_repack16(smem, NSTR, N_ALO, acc, m0, wm, ppb0, pc, nullptr, wn, lane);

    CP_WAIT0(); __syncthreads();
    mma_span16(sb, sb + N_ALO, sB, sB + N_BPL, NSTR, 272, 8, acc, wm, wn, lane);
    __syncthreads();
    float* stage = (float*)(smem + N_B0);
    #pragma unroll
    for (int st = 0; st < 2; st++) {
        int n = wn * 16 + st * 8 + ((lane & 3) << 1);
        float b0 = __ldg(ppb1 + n), b1 = __ldg(ppb1 + n + 1);
        int r0 = wm * 16 + (lane >> 2);
        #pragma unroll
        for (int h = 0; h < 2; h++) {
            int r = r0 + h * 8;
            stage[r * 132 + n]     = fmaxf(acc[st][h * 2 + 0] + b0, 0.f);
            stage[r * 132 + n + 1] = fmaxf(acc[st][h * 2 + 1] + b1, 0.f);
        }
    }
    __syncthreads();
    if (tid < 96) {
        int m = tid / 3, n = tid - (tid / 3) * 3;
        const float* aa = stage + m * 132;
        float s = __ldg(ppb2 + n);
        #pragma unroll 16
        for (int k = 0; k < 128; k++) s += aa[k] * __ldg(ppW2 + k * 3 + n);
        out[(size_t)(m0 + m) * 3 + n] = s;
    }
}

// ---------------- launch ----------------
extern "C" void kernel_launch(void* const* d_in, const int* in_sizes, int n_in,
                              void* d_out, int out_size)
{
    const float* x    = (const float*)d_in[0];
    const float* Rr   = (const float*)d_in[1];
    const float* Rs   = (const float*)d_in[2];
    const float* neW0 = (const float*)d_in[4];  const float* neb0 = (const float*)d_in[5];
    const float* neW1 = (const float*)d_in[6];  const float* neb1 = (const float*)d_in[7];
    const float* neW2 = (const float*)d_in[8];  const float* neb2 = (const float*)d_in[9];
    const float* eeW0 = (const float*)d_in[10]; const float* eeb0 = (const float*)d_in[11];
    const float* eeW1 = (const float*)d_in[12]; const float* eeb1 = (const float*)d_in[13];
    const float* eeW2 = (const float*)d_in[14]; const float* eeb2 = (const float*)d_in[15];
    const float* npW  = (const float*)d_in[16]; const float* npb  = (const float*)d_in[17];
    const float* epW  = (const float*)d_in[18]; const float* epb  = (const float*)d_in[19];
    const float* ppW0 = (const float*)d_in[20]; const float* ppb0 = (const float*)d_in[21];
    const float* ppW1 = (const float*)d_in[22]; const float* ppb1 = (const float*)d_in[23];
    const float* ppW2 = (const float*)d_in[24]; const float* ppb2 = (const float*)d_in[25];
    float* out = (float*)d_out;

    uint32_t* arena; cudaGetSymbolAddress((void**)&arena, g_arena);
    int* recv; cudaGetSymbolAddress((void**)&recv, g_recv);
    int* send; cudaGetSymbolAddress((void**)&send, g_send);
    __nv_bfloat16* whi; cudaGetSymbolAddress((void**)&whi, g_whi);
    __nv_bfloat16* wlo; cudaGetSymbolAddress((void**)&wlo, g_wlo);

    uint32_t* neb    = arena + OFF_NEB;
    float*    nef    = (float*)(arena + OFF_NEF);
    float*    nf1f   = (float*)(arena + OFF_NF1F);
    float*    pc     = (float*)(arena + OFF_PC);
    float*    agg0   = (float*)(arena + OFF_AGG0);
    float*    agg1   = (float*)(arena + OFF_AGG1);
    float*    prs    = (float*)(arena + OFF_PRS);
    float*    prpspA = (float*)(arena + OFF_PRPSPA);
    float*    prpspB = (float*)(arena + OFF_PRPSPB);
    float*    ec     = (float*)(arena + OFF_EC);

    const int WO[12] = {0,8192,24576,40960,57344,73728,90112,106496,139264,172032,188416,204800};

    static bool s_init = false;
    static cudaStream_t s1, s2;
    static cudaEvent_t evStart, evPrep, evS1, evNE;
    if (!s_init) {
        cudaStreamCreateWithFlags(&s1, cudaStreamNonBlocking);
        cudaStreamCreateWithFlags(&s2, cudaStreamNonBlocking);
        cudaEventCreateWithFlags(&evStart, cudaEventDisableTiming);
        cudaEventCreateWithFlags(&evPrep,  cudaEventDisableTiming);
        cudaEventCreateWithFlags(&evS1,    cudaEventDisableTiming);
        cudaEventCreateWithFlags(&evNE,    cudaEventDisableTiming);
        cudaFuncSetAttribute(node_mega,       cudaFuncAttributeMaxDynamicSharedMemorySize, NM_SMEM);
        cudaFuncSetAttribute(edge_mega,       cudaFuncAttributeMaxDynamicSharedMemorySize, EM_SMEM);
        cudaFuncSetAttribute(np_prpsp_kernel, cudaFuncAttributeMaxDynamicSharedMemorySize, NT_SMEM);
        cudaFuncSetAttribute(tail_kernel,     cudaFuncAttributeMaxDynamicSharedMemorySize, NT_SMEM);
        s_init = true;
    }

    // fork at root: extract + agg zeros on s1
    cudaEventRecord(evStart, 0);
    cudaStreamWaitEvent(s1, evStart, 0);
    extract_idx2_kernel<<<2 * BE / 8, 256, 0, s1>>>(Rr, Rs, recv, send);
    cudaMemsetAsync(agg0, 0, (size_t)2 * BN * 128 * sizeof(float), s1);
    cudaEventRecord(evS1, s1);

    // origin: weight prep
    PArg pa;
    pa.W[0] = neW0; pa.W[1] = neW1; pa.W[2] = neW2;
    pa.W[3] = eeW0; pa.W[4] = eeW1; pa.W[5] = eeW2;
    pa.W[6] = epW;  pa.W[7] = epW;  pa.W[8] = npW;
    pa.W[9] = ppW0; pa.W[10] = ppW0; pa.W[11] = ppW1;
    prep_weights<<<dim3(12, 8), 256>>>(pa, whi, wlo);
    cudaEventRecord(evPrep, 0);
    cudaStreamWaitEvent(s2, evPrep, 0);

    // s2: fused node mega-chain (PrPs + encoder + projections + pc), 256 threads
    {
        NodeArg na;
        na.x = x;
        na.eerh = whi + WO[3];        na.eerl = wlo + WO[3];
        na.eesh = whi + WO[3] + 8192; na.eesl = wlo + WO[3] + 8192;
        na.w0h = whi + WO[0]; na.w0l = wlo + WO[0];
        na.w1h = whi + WO[1]; na.w1l = wlo + WO[1];
        na.w2h = whi + WO[2]; na.w2l = wlo + WO[2];
        na.eprh = whi + WO[7];          na.eprl = wlo + WO[7];
        na.epsh = whi + WO[7] + 16384;  na.epsl = wlo + WO[7] + 16384;
        na.pqh = whi + WO[9];  na.pql = wlo + WO[9];
        na.b0 = neb0; na.b1 = neb1; na.b2 = neb2;
        na.neb = neb; na.nef = nef; na.prs = prs; na.prpsp = prpspA; na.pc = pc;
        node_mega<<<BN / 32, 256, NM_SMEM, s2>>>(na);
    }
    cudaEventRecord(evNE, s2);

    // join: indices + node outputs
    cudaStreamWaitEvent(0, evS1, 0);
    cudaStreamWaitEvent(0, evNE, 0);

    // fused edge chain + step-0 scatter (128-row tiles, mt=4, 256 threads)
    {
        EdgeArg ea;
        ea.prs = prs; ea.recv = recv; ea.send = send; ea.eeb0 = eeb0;
        ea.w1h = whi + WO[4]; ea.w1l = wlo + WO[4];
        ea.w2h = whi + WO[5]; ea.w2l = wlo + WO[5];
        ea.weh = whi + WO[6]; ea.wel = wlo + WO[6];
        ea.b1 = eeb1; ea.b2 = eeb2;
        ea.prpsp = prpspA; ea.epb = epb;
        ea.ec = ec; ea.agg = agg0;
        edge_mega<<<BE / 128, 256, EM_SMEM>>>(ea);
    }

    // fused np(step0) + prpsp(step1), pipelined weights
    np_prpsp_kernel<<<BN / 32, 512, NT_SMEM>>>(neb, agg0, nef,
        whi + WO[8], wlo + WO[8], npb, whi + WO[7], wlo + WO[7],
        nf1f, prpspB);

    // step-1 scatter (vectorized, v4 reductions)
    fused_scatter_kernel<<<BE * 32 / 256, 256>>>(ec, prpspB, recv, send, epb, agg1);

    // fused np(step1) + predictor + output, pipelined weights
    tail_kernel<<<BN / 32, 512, NT_SMEM>>>(neb, agg1, nf1f,
        whi + WO[8], wlo + WO[8], npb, pc,
        whi + WO[10], wlo + WO[10], ppb0,
        whi + WO[11], wlo + WO[11], ppb1,
        ppW2, ppb2, out);
}

// round 17
// speedup vs baseline: 1.0311x; 1.0174x over previous
#include <cuda_runtime.h>
#include <cuda_bf16.h>
#include <cstdint>

// ---------------- problem dims ----------------
#define Nn 1024
#define Ee 8192
#define BN 4096    // B*N
#define BE 32768   // B*E

// ---------------- device scratch ----------------
#define OFF_NEB    ((size_t)0)                       // node_enc bfp
#define OFF_NEF    (OFF_NEB + (size_t)BN*128)        // node_enc f32
#define OFF_NF1F   (OFF_NEF + (size_t)BN*128)        // nf1 f32
#define OFF_PC     (OFF_NF1F + (size_t)BN*128)       // neb@pp0a f32
#define OFF_NPC    (OFF_PC + (size_t)BN*128)         // neb@np_top f32
#define OFF_AGG0   (OFF_NPC + (size_t)BN*128)
#define OFF_AGG1   (OFF_AGG0 + (size_t)BN*128)       // adjacent to agg0
#define OFF_PRS    (OFF_AGG1 + (size_t)BN*128)       // [BN,256] f32 (x@Wr | x@Ws)
#define OFF_PRPSPA (OFF_PRS + (size_t)BN*256)        // [BN,256] f32 step0
#define OFF_PRPSPB (OFF_PRPSPA + (size_t)BN*256)     // [BN,256] f32 step1
#define OFF_EC     (OFF_PRPSPB + (size_t)BN*256)     // [BE,128] f32
#define ARENA_U32  (OFF_EC + (size_t)BE*128)

__device__ uint32_t g_arena[ARENA_U32];
__device__ int g_recv[BE];
__device__ int g_send[BE];
__device__ float g_zero[256];

// split/transposed weights [n][kpad] bf16, 12 matrices
#define WT_TOTAL 221184
__device__ __nv_bfloat16 g_whi[WT_TOTAL];
__device__ __nv_bfloat16 g_wlo[WT_TOTAL];

// ---------------- helpers ----------------
__device__ __forceinline__ uint32_t smem_u32(const void* p) {
    uint32_t a;
    asm("{ .reg .u64 t; cvta.to.shared.u64 t, %1; cvt.u32.u64 %0, t; }" : "=r"(a) : "l"(p));
    return a;
}

#define LDMX4(r, ad) \
    asm volatile("ldmatrix.sync.aligned.m8n8.x4.shared.b16 {%0,%1,%2,%3}, [%4];" \
        : "=r"((r)[0]), "=r"((r)[1]), "=r"((r)[2]), "=r"((r)[3]) : "r"(ad))

#define MMA16816(d, av, bv) \
    asm volatile("mma.sync.aligned.m16n8k16.row.col.f32.bf16.bf16.f32 " \
        "{%0,%1,%2,%3},{%4,%5,%6,%7},{%8,%9},{%0,%1,%2,%3};" \
        : "+f"((d)[0]), "+f"((d)[1]), "+f"((d)[2]), "+f"((d)[3]) \
        : "r"((av)[0]), "r"((av)[1]), "r"((av)[2]), "r"((av)[3]), \
          "r"((bv)[0]), "r"((bv)[1]))

#define CP_ASYNC16(sa, gp) \
    asm volatile("cp.async.cg.shared.global [%0], [%1], 16;" :: "r"(sa), "l"(gp))
#define CP_COMMIT()  asm volatile("cp.async.commit_group;" ::: "memory")
#define CP_WAIT1()   asm volatile("cp.async.wait_group 1;" ::: "memory")
#define CP_WAIT0()   asm volatile("cp.async.wait_group 0;" ::: "memory")

#define REDV2(ptr, v0, v1) \
    asm volatile("red.global.add.v2.f32 [%0], {%1, %2};" \
        :: "l"(ptr), "f"(v0), "f"(v1) : "memory")
#define REDV4(ptr, v0, v1, v2, v3) \
    asm volatile("red.global.add.v4.f32 [%0], {%1, %2, %3, %4};" \
        :: "l"(ptr), "f"(v0), "f"(v1), "f"(v2), "f"(v3) : "memory")

__device__ __forceinline__ uint32_t packbfp(float v) {
    __nv_bfloat16 h = __float2bfloat16(v);
    float hf = __bfloat162float(h);
    __nv_bfloat16 l = __float2bfloat16(v - hf);
    return (uint32_t)__bfloat16_as_ushort(h) | ((uint32_t)__bfloat16_as_ushort(l) << 16);
}

// ---- 32-col-warp 3-pass MMA (node_mega, 256 threads) ----
__device__ __forceinline__ void mma_span1(
    uint32_t aHi, uint32_t aLo, uint32_t bHi, uint32_t bLo,
    int astr, int bstr, int nk, float (*acc)[4], int tile, int wn, int lane)
{
    for (int ks = 0; ks < nk; ks++) {
        uint32_t bh[8], bl[8];
        #pragma unroll
        for (int np = 0; np < 2; np++) {
            int n = wn * 32 + np * 16 + ((lane >> 4) << 3) + (lane & 7);
            int koff = ((lane >> 3) & 1) << 3;
            uint32_t ad = bHi + n * bstr + (ks * 16 + koff) * 2;
            LDMX4(&bh[np * 4], ad);
            LDMX4(&bl[np * 4], ad + (bLo - bHi));
        }
        int r = tile * 16 + (lane & 15);
        int koff = (lane >> 4) << 3;
        uint32_t ad = aHi + r * astr + (ks * 16 + koff) * 2;
        uint32_t ah[4], al[4];
        LDMX4(ah, ad);
        LDMX4(al, ad + (aLo - aHi));
        #pragma unroll
        for (int st = 0; st < 4; st++) {
            MMA16816(acc[st], ah, &bh[st * 2]);
            MMA16816(acc[st], ah, &bl[st * 2]);
            MMA16816(acc[st], al, &bh[st * 2]);
        }
    }
}

// ---- 32-col-warp, 4 m-tiles per warp (edge_mega, 256 threads) ----
__device__ __forceinline__ void mma_span_mt4(
    uint32_t aHi, uint32_t aLo, uint32_t bHi, uint32_t bLo,
    int astr, int bstr, int nk, float acc[4][4][4],
    int tile0, int wn, int lane)
{
    for (int ks = 0; ks < nk; ks++) {
        uint32_t bh[8], bl[8];
        #pragma unroll
        for (int np = 0; np < 2; np++) {
            int n = wn * 32 + np * 16 + ((lane >> 4) << 3) + (lane & 7);
            int koff = ((lane >> 3) & 1) << 3;
            uint32_t ad = bHi + n * bstr + (ks * 16 + koff) * 2;
            LDMX4(&bh[np * 4], ad);
            LDMX4(&bl[np * 4], ad + (bLo - bHi));
        }
        int koff = (lane >> 4) << 3;
        uint32_t ah[4][4], al[4][4];
        #pragma unroll
        for (int mt = 0; mt < 4; mt++) {
            int r = (tile0 + mt) * 16 + (lane & 15);
            uint32_t ad = aHi + r * astr + (ks * 16 + koff) * 2;
            LDMX4(ah[mt], ad);
            LDMX4(al[mt], ad + (aLo - aHi));
        }
        #pragma unroll
        for (int st = 0; st < 4; st++)
            #pragma unroll
            for (int mt = 0; mt < 4; mt++) {
                MMA16816(acc[mt][st], ah[mt], &bh[st * 2]);
                MMA16816(acc[mt][st], ah[mt], &bl[st * 2]);
                MMA16816(acc[mt][st], al[mt], &bh[st * 2]);
            }
    }
}

// ---- 16-col-warp 3-pass MMA (np/tail kernels, 512 threads): wn in 0..7 ----
__device__ __forceinline__ void mma_span16(
    uint32_t aHi, uint32_t aLo, uint32_t bHi, uint32_t bLo,
    int astr, int bstr, int nk, float (*acc)[4], int tile, int wn, int lane)
{
    for (int ks = 0; ks < nk; ks++) {
        uint32_t bh[4], bl[4];
        int n = wn * 16 + ((lane >> 4) << 3) + (lane & 7);
        int koff = ((lane >> 3) & 1) << 3;
        uint32_t ad = bHi + n * bstr + (ks * 16 + koff) * 2;
        LDMX4(bh, ad);
        LDMX4(bl, ad + (bLo - bHi));
        int r = tile * 16 + (lane & 15);
        int koff2 = (lane >> 4) << 3;
        uint32_t ad2 = aHi + r * astr + (ks * 16 + koff2) * 2;
        uint32_t ah[4], al[4];
        LDMX4(ah, ad2);
        LDMX4(al, ad2 + (aLo - aHi));
        #pragma unroll
        for (int st = 0; st < 2; st++) {
            MMA16816(acc[st], ah, &bh[st * 2]);
            MMA16816(acc[st], ah, &bl[st * 2]);
            MMA16816(acc[st], al, &bh[st * 2]);
        }
    }
}

// async weight load with K-window (cp.async, caller commits/waits)
__device__ __forceinline__ void load_Bw_cp(uint32_t sbase, int plane,
    const __nv_bfloat16* Bhi, const __nv_bfloat16* Blo,
    int nrows, int kwin, int fullK, int k0, int bstr, int tid, int nth)
{
    int kg = kwin >> 3;
    int per = nrows * kg;
    for (int item = tid; item < per; item += nth) {
        int n = item / kg, g = item - n * kg;
        size_t goff = (size_t)n * fullK + k0 + (g << 3);
        uint32_t so = sbase + n * bstr + (g << 4);
        CP_ASYNC16(so, Bhi + goff);
        CP_ASYNC16(so + plane, Blo + goff);
    }
}

// 32-col-warp epilogue, full-featured (node_mega)
__device__ __forceinline__ void epi_repack2(char* smem, int astr, int aplane,
    float (*acc)[4], int m0, int tile,
    const float* bias, const float* resid, float* outf, uint32_t* outb,
    int wn, int lane)
{
    #pragma unroll
    for (int st = 0; st < 4; st++) {
        int n = wn * 32 + st * 8 + ((lane & 3) << 1);
        float b0 = __ldg(bias + n), b1 = __ldg(bias + n + 1);
        int r0 = tile * 16 + (lane >> 2);
        #pragma unroll
        for (int h = 0; h < 2; h++) {
            int r = r0 + h * 8;
            float s0 = acc[st][h * 2 + 0] + b0;
            float s1 = acc[st][h * 2 + 1] + b1;
            if (resid) {
                float2 rv = *(const float2*)(resid + (((size_t)(m0 + r)) << 7) + n);
                s0 += rv.x; s1 += rv.y;
            }
            s0 = fmaxf(s0, 0.f); s1 = fmaxf(s1, 0.f);
            if (outf) *(float2*)(outf + (((size_t)(m0 + r)) << 7) + n) = make_float2(s0, s1);
            uint32_t p0 = packbfp(s0), p1 = packbfp(s1);
            if (outb) *(uint2*)(outb + (((size_t)(m0 + r)) << 7) + n) = make_uint2(p0, p1);
            int off = r * astr + n * 2;
            *(uint32_t*)(smem + off) = (p0 & 0xffffu) | (p1 << 16);
            *(uint32_t*)(smem + aplane + off) = (p0 >> 16) | (p1 & 0xffff0000u);
            acc[st][h * 2 + 0] = 0.f;
            acc[st][h * 2 + 1] = 0.f;
        }
    }
}

// 32-col-warp epilogue, bias-only (edge_mega)
__device__ __forceinline__ void epi_repack2e(char* smem, int astr, int aplane,
    float (*acc)[4], int tile, const float* bias, int wn, int lane)
{
    #pragma unroll
    for (int st = 0; st < 4; st++) {
        int n = wn * 32 + st * 8 + ((lane & 3) << 1);
        float b0 = __ldg(bias + n), b1 = __ldg(bias + n + 1);
        int r0 = tile * 16 + (lane >> 2);
        #pragma unroll
        for (int h = 0; h < 2; h++) {
            int r = r0 + h * 8;
            float s0 = fmaxf(acc[st][h * 2 + 0] + b0, 0.f);
            float s1 = fmaxf(acc[st][h * 2 + 1] + b1, 0.f);
            uint32_t p0 = packbfp(s0), p1 = packbfp(s1);
            int off = r * astr + n * 2;
            *(uint32_t*)(smem + off) = (p0 & 0xffffu) | (p1 << 16);
            *(uint32_t*)(smem + aplane + off) = (p0 >> 16) | (p1 & 0xffff0000u);
            acc[st][h * 2 + 0] = 0.f;
            acc[st][h * 2 + 1] = 0.f;
        }
    }
}

// 16-col-warp epilogue (two optional f32 resids, optional f32 out)
__device__ __forceinline__ void epi_repack16(char* smem, int astr, int aplane,
    float (*acc)[4], int m0, int tile,
    const float* bias, const float* resid, const float* resid2, float* outf,
    int wn, int lane)
{
    #pragma unroll
    for (int st = 0; st < 2; st++) {
        int n = wn * 16 + st * 8 + ((lane & 3) << 1);
        float b0 = __ldg(bias + n), b1 = __ldg(bias + n + 1);
        int r0 = tile * 16 + (lane >> 2);
        #pragma unroll
        for (int h = 0; h < 2; h++) {
            int r = r0 + h * 8;
            float s0 = acc[st][h * 2 + 0] + b0;
            float s1 = acc[st][h * 2 + 1] + b1;
            if (resid) {
                float2 rv = *(const float2*)(resid + (((size_t)(m0 + r)) << 7) + n);
                s0 += rv.x; s1 += rv.y;
            }
            if (resid2) {
                float2 rv = *(const float2*)(resid2 + (((size_t)(m0 + r)) << 7) + n);
                s0 += rv.x; s1 += rv.y;
            }
            s0 = fmaxf(s0, 0.f); s1 = fmaxf(s1, 0.f);
            if (outf) *(float2*)(outf + (((size_t)(m0 + r)) << 7) + n) = make_float2(s0, s1);
            uint32_t p0 = packbfp(s0), p1 = packbfp(s1);
            int off = r * astr + n * 2;
            *(uint32_t*)(smem + off) = (p0 & 0xffffu) | (p1 << 16);
            *(uint32_t*)(smem + aplane + off) = (p0 >> 16) | (p1 & 0xffff0000u);
            acc[st][h * 2 + 0] = 0.f;
            acc[st][h * 2 + 1] = 0.f;
        }
    }
}

// write acc f32 (32-col warps)
__device__ __forceinline__ void write_accf(float (*acc)[4], int m0, int tile,
    int wn, int lane, float* out, int nbase, int ldo)
{
    #pragma unroll
    for (int st = 0; st < 4; st++) {
        int n = nbase + wn * 32 + st * 8 + ((lane & 3) << 1);
        int r0 = tile * 16 + (lane >> 2);
        #pragma unroll
        for (int h = 0; h < 2; h++) {
            int m = m0 + r0 + h * 8;
            *(float2*)(out + (size_t)m * ldo + n) =
                make_float2(acc[st][h * 2 + 0], acc[st][h * 2 + 1]);
            acc[st][h * 2 + 0] = 0.f;
            acc[st][h * 2 + 1] = 0.f;
        }
    }
}

// write acc f32 (16-col warps)
__device__ __forceinline__ void write_accf16(float (*acc)[4], int m0, int tile,
    int wn, int lane, float* out, int nbase, int ldo)
{
    #pragma unroll
    for (int st = 0; st < 2; st++) {
        int n = nbase + wn * 16 + st * 8 + ((lane & 3) << 1);
        int r0 = tile * 16 + (lane >> 2);
        #pragma unroll
        for (int h = 0; h < 2; h++) {
            int m = m0 + r0 + h * 8;
            *(float2*)(out + (size_t)m * ldo + n) =
                make_float2(acc[st][h * 2 + 0], acc[st][h * 2 + 1]);
            acc[st][h * 2 + 0] = 0.f;
            acc[st][h * 2 + 1] = 0.f;
        }
    }
}

// ---------------- aux kernels ----------------
__global__ void extract_idx2_kernel(const float* __restrict__ Rr,
                                    const float* __restrict__ Rs,
                                    int* __restrict__ recv, int* __restrict__ send)
{
    int row = blockIdx.x * 8 + (threadIdx.x >> 5);
    int lane = threadIdx.x & 31;
    const float* R = (row < BE) ? Rr : Rs;
    int r = (row < BE) ? row : row - BE;
    const float4* p = (const float4*)(R + (size_t)r * Nn);
    int found = -1;
    #pragma unroll
    for (int i = 0; i < 4; i++) {
        int q = lane + i * 32;
        float4 v = p[q];
        if (v.x > 0.5f) found = q * 4 + 0;
        if (v.y > 0.5f) found = q * 4 + 1;
        if (v.z > 0.5f) found = q * 4 + 2;
        if (v.w > 0.5f) found = q * 4 + 3;
    }
    if (__ballot_sync(0xFFFFFFFFu, found >= 0) == 0u) {
        #pragma unroll
        for (int i = 4; i < 8; i++) {
            int q = lane + i * 32;
            float4 v = p[q];
            if (v.x > 0.5f) found = q * 4 + 0;
            if (v.y > 0.5f) found = q * 4 + 1;
            if (v.z > 0.5f) found = q * 4 + 2;
            if (v.w > 0.5f) found = q * 4 + 3;
        }
    }
    #pragma unroll
    for (int o = 16; o; o >>= 1) found = max(found, __shfl_xor_sync(0xFFFFFFFFu, found, o));
    if (lane == 0) {
        found = max(found, 0);
        if (row < BE) recv[r] = found; else send[r] = found;
    }
}

// matrices: 0 ne0 1 ne1 2 ne2 3 eers(R256) 4 ee1 5 ee2 6 ep_e 7 ep_rs(R256)
//           8 np(K256) 9 pp0a 10 pp0b 11 pp1
struct PArg { const float* W[12]; };
__constant__ int c_Ks[12]  = {32,128,128, 32,128,128,128,128,256,128,128,128};
__constant__ int c_Kps[12] = {64,128,128, 64,128,128,128,128,256,128,128,128};
__constant__ int c_Rs[12]  = {128,128,128,256,128,128,128,256,128,128,128,128};
__constant__ int c_r0a[12] = {0,0,0,0,0,0,0,128,0,0,128,0};
__constant__ int c_r0b[12] = {0,0,0,32,0,0,0,256,0,0,0,0};
__constant__ int c_off[12] = {0,8192,24576,40960,57344,73728,90112,106496,139264,172032,188416,204800};

__global__ void prep_weights(PArg a, __nv_bfloat16* __restrict__ hi, __nv_bfloat16* __restrict__ lo)
{
    int mid = blockIdx.x;
    int K = c_Ks[mid], Kp = c_Kps[mid], R = c_Rs[mid];
    int r0a = c_r0a[mid], r0b = c_r0b[mid];
    const float* W = a.W[mid];
    __nv_bfloat16* dh = hi + c_off[mid];
    __nv_bfloat16* dl = lo + c_off[mid];
    int total = R * Kp;
    for (int i = threadIdx.x + blockIdx.y * blockDim.x; i < total; i += blockDim.x * gridDim.y) {
        int n = i / Kp, k = i - n * Kp;
        int col = n & 127;
        int r0 = (n >> 7) ? r0b : r0a;
        float v = (k < K) ? W[(size_t)(r0 + k) * 128 + col] : 0.f;
        __nv_bfloat16 h = __float2bfloat16(v);
        dh[i] = h;
        dl[i] = __float2bfloat16(v - __bfloat162float(h));
    }
}

// step-1 scatter: 4 h-values per thread, vector reduction
__global__ void fused_scatter_kernel(const float* __restrict__ ec,
                                     const float* __restrict__ prpsp,
                                     const int* __restrict__ recv,
                                     const int* __restrict__ send,
                                     const float* __restrict__ bias,
                                     float* __restrict__ agg)
{
    int t = blockIdx.x * blockDim.x + threadIdx.x;   // BE*32
    if (t >= BE * 32) return;
    int e = t >> 5, q = t & 31;
    int h = q << 2;
    int bo = (e >> 13) << 10;
    int r = __ldg(recv + e) + bo, s = __ldg(send + e) + bo;
    float4 ev = *(const float4*)(ec + ((size_t)e << 7) + h);
    float4 pr = *(const float4*)(prpsp + (size_t)r * 256 + h);
    float4 ps = *(const float4*)(prpsp + (size_t)s * 256 + 128 + h);
    float4 bb = *(const float4*)(bias + h);
    float v0 = fmaxf(ev.x + pr.x + ps.x + bb.x, 0.f);
    float v1 = fmaxf(ev.y + pr.y + ps.y + bb.y, 0.f);
    float v2 = fmaxf(ev.z + pr.z + ps.z + bb.z, 0.f);
    float v3 = fmaxf(ev.w + pr.w + ps.w + bb.w, 0.f);
    REDV4(agg + (size_t)r * 128 + h, v0, v1, v2, v3);
}

// ---------------- node_mega: eer,ees,ne0..ne2,epr,eps,pc,npc (256 thr, ping-pong) ----------------
#define NM_STR   272
#define NM_ALO   (32 * NM_STR)
#define NM_B0    (2 * NM_ALO)
#define NM_BPL   (128 * NM_STR)
#define NM_SLOT  (2 * NM_BPL)
#define NM_SMEM  (NM_B0 + 2 * NM_SLOT)     // 156672

struct NodeArg {
    const float* x;
    const __nv_bfloat16 *eerh,*eerl,*eesh,*eesl;
    const __nv_bfloat16 *w0h,*w0l,*w1h,*w1l,*w2h,*w2l,*eprh,*eprl,*epsh,*epsl,*pqh,*pql;
    const __nv_bfloat16 *nph,*npl;     // np (K=256), top half used here
    const float *b0,*b1,*b2;
    uint32_t* neb; float* nef; float* prs; float* prpsp; float* pc; float* npc;
};

__global__ __launch_bounds__(256) void node_mega(NodeArg a)
{
    extern __shared__ char smem[];
    const uint32_t sb = smem_u32(smem);
    const int tid = threadIdx.x;
    const int wid = tid >> 5, lane = tid & 31;
    const int wm = wid & 1, wn = wid >> 1;
    const int m0 = blockIdx.x * 32;

    const uint32_t sA = sb + NM_B0;
    const uint32_t sB = sb + NM_B0 + NM_SLOT;

    float acc[4][4];
    #pragma unroll
    for (int st = 0; st < 4; st++)
        #pragma unroll
        for (int r = 0; r < 4; r++) acc[st][r] = 0.f;

    load_Bw_cp(sA, NM_BPL, a.eerh, a.eerl, 128, 64, 64, 0, NM_STR, tid, 256); CP_COMMIT();
    load_Bw_cp(sB, NM_BPL, a.eesh, a.eesl, 128, 64, 64, 0, NM_STR, tid, 256); CP_COMMIT();

    #pragma unroll
    for (int it = 0; it < 2; it++) {
        int item = tid + (it << 8);
        int r = item >> 4, g = item & 15;
        int kc = g << 2;
        uint32_t p0 = 0, p1 = 0, p2 = 0, p3 = 0;
        if (kc < 32) {
            float4 v = *(const float4*)(a.x + (size_t)(m0 + r) * 32 + kc);
            p0 = packbfp(v.x); p1 = packbfp(v.y); p2 = packbfp(v.z); p3 = packbfp(v.w);
        }
        uint32_t hi01 = (p0 & 0xffffu) | (p1 << 16);
        uint32_t hi23 = (p2 & 0xffffu) | (p3 << 16);
        uint32_t lo01 = (p0 >> 16) | (p1 & 0xffff0000u);
        uint32_t lo23 = (p2 >> 16) | (p3 & 0xffff0000u);
        int off = r * NM_STR + g * 8;
        *(uint2*)(smem + off) = make_uint2(hi01, hi23);
        *(uint2*)(smem + NM_ALO + off) = make_uint2(lo01, lo23);
    }

    // P0: eer -> prs[:,0:128]
    CP_WAIT1(); __syncthreads();
    mma_span1(sb, sb + NM_ALO, sA, sA + NM_BPL, NM_STR, NM_STR, 4, acc, wm, wn, lane);
    __syncthreads();
    write_accf(acc, m0, wm, wn, lane, a.prs, 0, 256);
    load_Bw_cp(sA, NM_BPL, a.w0h, a.w0l, 128, 64, 64, 0, NM_STR, tid, 256); CP_COMMIT();

    // P1: ees -> prs[:,128:256]
    CP_WAIT1(); __syncthreads();
    mma_span1(sb, sb + NM_ALO, sB, sB + NM_BPL, NM_STR, NM_STR, 4, acc, wm, wn, lane);
    __syncthreads();
    write_accf(acc, m0, wm, wn, lane, a.prs, 128, 256);
    load_Bw_cp(sB, NM_BPL, a.w1h, a.w1l, 128, 128, 128, 0, NM_STR, tid, 256); CP_COMMIT();

    // P2: ne0
    CP_WAIT1(); __syncthreads();
    mma_span1(sb, sb + NM_ALO, sA, sA + NM_BPL, NM_STR, NM_STR, 4, acc, wm, wn, lane);
    __syncthreads();
    epi_repack2(smem, NM_STR, NM_ALO, acc, m0, wm, a.b0, nullptr, nullptr, nullptr, wn, lane);
    load_Bw_cp(sA, NM_BPL, a.w2h, a.w2l, 128, 128, 128, 0, NM_STR, tid, 256); CP_COMMIT();

    // P3: ne1
    CP_WAIT1(); __syncthreads();
    mma_span1(sb, sb + NM_ALO, sB, sB + NM_BPL, NM_STR, NM_STR, 8, acc, wm, wn, lane);
    __syncthreads();
    epi_repack2(smem, NM_STR, NM_ALO, acc, m0, wm, a.b1, nullptr, nullptr, nullptr, wn, lane);
    load_Bw_cp(sB, NM_BPL, a.eprh, a.eprl, 128, 128, 128, 0, NM_STR, tid, 256); CP_COMMIT();

    // P4: ne2 -> neb/nef
    CP_WAIT1(); __syncthreads();
    mma_span1(sb, sb + NM_ALO, sA, sA + NM_BPL, NM_STR, NM_STR, 8, acc, wm, wn, lane);
    __syncthreads();
    epi_repack2(smem, NM_STR, NM_ALO, acc, m0, wm, a.b2, nullptr, a.nef, a.neb, wn, lane);
    load_Bw_cp(sA, NM_BPL, a.epsh, a.epsl, 128, 128, 128, 0, NM_STR, tid, 256); CP_COMMIT();

    // P5: epr -> prpspA[:,0:128]
    CP_WAIT1(); __syncthreads();
    mma_span1(sb, sb + NM_ALO, sB, sB + NM_BPL, NM_STR, NM_STR, 8, acc, wm, wn, lane);
    __syncthreads();
    write_accf(acc, m0, wm, wn, lane, a.prpsp, 0, 256);
    load_Bw_cp(sB, NM_BPL, a.pqh, a.pql, 128, 128, 128, 0, NM_STR, tid, 256); CP_COMMIT();

    // P6: eps -> prpspA[:,128:256]
    CP_WAIT1(); __syncthreads();
    mma_span1(sb, sb + NM_ALO, sA, sA + NM_BPL, NM_STR, NM_STR, 8, acc, wm, wn, lane);
    __syncthreads();
    write_accf(acc, m0, wm, wn, lane, a.prpsp, 128, 256);
    load_Bw_cp(sA, NM_BPL, a.nph, a.npl, 128, 128, 256, 0, NM_STR, tid, 256); CP_COMMIT();

    // P7: pc (pq in sB)
    CP_WAIT1(); __syncthreads();
    mma_span1(sb, sb + NM_ALO, sB, sB + NM_BPL, NM_STR, NM_STR, 8, acc, wm, wn, lane);
    __syncthreads();
    write_accf(acc, m0, wm, wn, lane, a.pc, 0, 128);

    // P8: npc = neb @ np_top (sA)
    CP_WAIT0(); __syncthreads();
    mma_span1(sb, sb + NM_ALO, sA, sA + NM_BPL, NM_STR, NM_STR, 8, acc, wm, wn, lane);
    __syncthreads();
    write_accf(acc, m0, wm, wn, lane, a.npc, 0, 128);
}

// ---------------- edge_mega: 128-row tiles, 256 thr, 2m x 4n warps (mt=4) ----------------
#define EM_STR   272
#define EM_APL   (128 * EM_STR)
#define EM_B0    (2 * EM_APL)
#define EM_BPL   (128 * EM_STR)
#define EM_SLOT  (2 * EM_BPL)
#define EM_SMEM  (EM_B0 + 2 * EM_SLOT)     // 208896

struct EdgeArg {
    const float* prs; const int* recv; const int* send; const float* eeb0;
    const __nv_bfloat16 *w1h,*w1l,*w2h,*w2l,*weh,*wel;
    const float *b1,*b2;
    const float* prpsp; const float* epb;
    float* ec; float* agg;
};

__global__ __launch_bounds__(256, 1) void edge_mega(EdgeArg a)
{
    extern __shared__ char smem[];
    const uint32_t sb = smem_u32(smem);
    const int tid = threadIdx.x;
    const int wid = tid >> 5, lane = tid & 31;
    const int wm = wid & 1, wn = wid >> 1;
    const int m0 = blockIdx.x * 128;

    const uint32_t sA = sb + EM_B0;
    const uint32_t sB = sb + EM_B0 + EM_SLOT;

    float acc[4][4][4];
    #pragma unroll
    for (int mt = 0; mt < 4; mt++)
        #pragma unroll
        for (int st = 0; st < 4; st++)
            #pragma unroll
            for (int r = 0; r < 4; r++) acc[mt][st][r] = 0.f;

    load_Bw_cp(sA, EM_BPL, a.w1h, a.w1l, 128, 128, 128, 0, EM_STR, tid, 256); CP_COMMIT();
    load_Bw_cp(sB, EM_BPL, a.w2h, a.w2l, 128, 128, 128, 0, EM_STR, tid, 256); CP_COMMIT();

    // A <- edge layer0 on the fly: relu(Pr[recv]+Ps[send]+b0), 128 rows x 128 cols
    #pragma unroll
    for (int it = 0; it < 16; it++) {
        int item = tid + (it << 8);
        int r = item >> 5, g = item & 31;
        int kc = g << 2;
        int m = m0 + r;
        int bo = (m >> 13) << 10;
        int rr = __ldg(a.recv + m) + bo, ss = __ldg(a.send + m) + bo;
        float4 pr = *(const float4*)(a.prs + (size_t)rr * 256 + kc);
        float4 ps = *(const float4*)(a.prs + (size_t)ss * 256 + 128 + kc);
        float4 bb = *(const float4*)(a.eeb0 + kc);
        uint32_t p0 = packbfp(fmaxf(pr.x + ps.x + bb.x, 0.f));
        uint32_t p1 = packbfp(fmaxf(pr.y + ps.y + bb.y, 0.f));
        uint32_t p2 = packbfp(fmaxf(pr.z + ps.z + bb.z, 0.f));
        uint32_t p3 = packbfp(fmaxf(pr.w + ps.w + bb.w, 0.f));
        uint32_t hi01 = (p0 & 0xffffu) | (p1 << 16);
        uint32_t hi23 = (p2 & 0xffffu) | (p3 << 16);
        uint32_t lo01 = (p0 >> 16) | (p1 & 0xffff0000u);
        uint32_t lo23 = (p2 >> 16) | (p3 & 0xffff0000u);
        int off = r * EM_STR + g * 8;
        *(uint2*)(smem + off) = make_uint2(hi01, hi23);
        *(uint2*)(smem + EM_APL + off) = make_uint2(lo01, lo23);
    }

    // phase 1: ee1 (sA)
    CP_WAIT1(); __syncthreads();
    mma_span_mt4(sb, sb + EM_APL, sA, sA + EM_BPL, EM_STR, EM_STR, 8,
                 acc, wm * 4, wn, lane);
    __syncthreads();
    #pragma unroll
    for (int mt = 0; mt < 4; mt++)
        epi_repack2e(smem, EM_STR, EM_APL, acc[mt], wm * 4 + mt, a.b1, wn, lane);
    load_Bw_cp(sA, EM_BPL, a.weh, a.wel, 128, 128, 128, 0, EM_STR, tid, 256); CP_COMMIT();

    // phase 2: ee2 (sB)
    CP_WAIT1(); __syncthreads();
    mma_span_mt4(sb, sb + EM_APL, sB, sB + EM_BPL, EM_STR, EM_STR, 8,
                 acc, wm * 4, wn, lane);
    __syncthreads();
    #pragma unroll
    for (int mt = 0; mt < 4; mt++)
        epi_repack2e(smem, EM_STR, EM_APL, acc[mt], wm * 4 + mt, a.b2, wn, lane);

    // phase 3: ec (sA)
    CP_WAIT0(); __syncthreads();
    mma_span_mt4(sb, sb + EM_APL, sA, sA + EM_BPL, EM_STR, EM_STR, 8,
                 acc, wm * 4, wn, lane);

    // epilogue: write ec + fused step-0 scatter (vector reductions)
    #pragma unroll
    for (int mt = 0; mt < 4; mt++) {
        int row0 = m0 + (wm * 4 + mt) * 16 + (lane >> 2);
        #pragma unroll
        for (int st = 0; st < 4; st++) {
            int n = wn * 32 + st * 8 + ((lane & 3) << 1);
            float e0b = __ldg(a.epb + n), e1b = __ldg(a.epb + n + 1);
            #pragma unroll
            for (int h = 0; h < 2; h++) {
                int m = row0 + h * 8;
                float e0 = acc[mt][st][h * 2 + 0];
                float e1 = acc[mt][st][h * 2 + 1];
                *(float2*)(a.ec + ((size_t)m << 7) + n) = make_float2(e0, e1);
                int bo = (m >> 13) << 10;
                int r_ = __ldg(a.recv + m) + bo, s_ = __ldg(a.send + m) + bo;
                float2 pr = *(const float2*)(a.prpsp + (size_t)r_ * 256 + n);
                float2 ps = *(const float2*)(a.prpsp + (size_t)s_ * 256 + 128 + n);
                float v0 = fmaxf(e0 + pr.x + ps.x + e0b, 0.f);
                float v1 = fmaxf(e1 + pr.y + ps.y + e1b, 0.f);
                REDV2(a.agg + (size_t)r_ * 128 + n, v0, v1);
            }
        }
    }
}

// ---------------- np_prpsp / tail (512 threads, ping-pong, K=128 A-tiles) ----------------
#define NSTR2   272
#define N2_ALO  (32 * NSTR2)                // 8704
#define N2_B0   (2 * N2_ALO)                // 17408
#define N2_BPL  (128 * NSTR2)               // 34816
#define N2_SLOT (2 * N2_BPL)                // 69632
#define NT_SMEM (N2_B0 + 2 * N2_SLOT)       // 156672

// A <- agg (f32 -> bfp), 32 rows x 128 cols; 512 threads
__device__ __forceinline__ void load_A_agg(char* smem, int m0,
    const float* agg, int tid)
{
    #pragma unroll
    for (int it = 0; it < 2; it++) {
        int item = tid + (it << 9);
        int r = item >> 5, g = item & 31;
        int kc = g << 2;
        int m = m0 + r;
        float4 v = *(const float4*)(agg + ((size_t)m << 7) + kc);
        uint32_t p0 = packbfp(v.x), p1 = packbfp(v.y), p2 = packbfp(v.z), p3 = packbfp(v.w);
        uint32_t hi01 = (p0 & 0xffffu) | (p1 << 16);
        uint32_t hi23 = (p2 & 0xffffu) | (p3 << 16);
        uint32_t lo01 = (p0 >> 16) | (p1 & 0xffff0000u);
        uint32_t lo23 = (p2 >> 16) | (p3 & 0xffff0000u);
        int off = r * NSTR2 + g * 8;
        *(uint2*)(smem + off) = make_uint2(hi01, hi23);
        *(uint2*)(smem + N2_ALO + off) = make_uint2(lo01, lo23);
    }
}

__global__ __launch_bounds__(512, 1) void np_prpsp_kernel(
    const float* __restrict__ agg,
    const float* __restrict__ npc, const float* __restrict__ nef,
    const __nv_bfloat16* __restrict__ npbh, const __nv_bfloat16* __restrict__ npbl, // np bottom half
    const float* __restrict__ npb,
    const __nv_bfloat16* __restrict__ epHi, const __nv_bfloat16* __restrict__ epLo,
    float* __restrict__ nf_out, float* __restrict__ prpsp_out)
{
    extern __shared__ char smem[];
    const uint32_t sb = smem_u32(smem);
    const int tid = threadIdx.x;
    const int wid = tid >> 5, lane = tid & 31;
    const int wm = wid & 1, wn = wid >> 1;
    const int m0 = blockIdx.x * 32;

    const uint32_t sA = sb + N2_B0;
    const uint32_t sB = sb + N2_B0 + N2_SLOT;

    float acc[2][4];
    #pragma unroll
    for (int st = 0; st < 2; st++)
        #pragma unroll
        for (int r = 0; r < 4; r++) acc[st][r] = 0.f;

    load_Bw_cp(sA, N2_BPL, npbh, npbl, 128, 128, 256, 128, NSTR2, tid, 512); CP_COMMIT();
    load_Bw_cp(sB, N2_BPL, epHi, epLo, 128, 128, 128, 0, NSTR2, tid, 512); CP_COMMIT();

    load_A_agg(smem, m0, agg, tid);

    // P1: agg @ np_bot; epi: +npb +npc +nef -> nf1 + repack
    CP_WAIT1(); __syncthreads();
    mma_span16(sb, sb + N2_ALO, sA, sA + N2_BPL, NSTR2, NSTR2, 8, acc, wm, wn, lane);
    __syncthreads();
    epi_repack16(smem, NSTR2, N2_ALO, acc, m0, wm, npb, npc, nef, nf_out, wn, lane);
    load_Bw_cp(sA, N2_BPL, epHi + 128 * 128, epLo + 128 * 128, 128, 128, 128, 0, NSTR2, tid, 512); CP_COMMIT();

    // P2: nf @ ep_r -> prpsp[:,0:128]
    CP_WAIT1(); __syncthreads();
    mma_span16(sb, sb + N2_ALO, sB, sB + N2_BPL, NSTR2, NSTR2, 8, acc, wm, wn, lane);
    __syncthreads();
    write_accf16(acc, m0, wm, wn, lane, prpsp_out, 0, 256);

    // P3: nf @ ep_s -> prpsp[:,128:256]
    CP_WAIT0(); __syncthreads();
    mma_span16(sb, sb + N2_ALO, sA, sA + N2_BPL, NSTR2, NSTR2, 8, acc, wm, wn, lane);
    __syncthreads();
    write_accf16(acc, m0, wm, wn, lane, prpsp_out, 128, 256);
}

__global__ __launch_bounds__(512, 1) void tail_kernel(
    const float* __restrict__ agg1,
    const float* __restrict__ npc, const float* __restrict__ nf1,
    const __nv_bfloat16* __restrict__ npbh, const __nv_bfloat16* __restrict__ npbl,
    const float* __restrict__ npb,
    const float* __restrict__ pc,
    const __nv_bfloat16* __restrict__ p0bHi, const __nv_bfloat16* __restrict__ p0bLo,
    const float* __restrict__ ppb0,
    const __nv_bfloat16* __restrict__ p1Hi, const __nv_bfloat16* __restrict__ p1Lo,
    const float* __restrict__ ppb1,
    const float* __restrict__ ppW2, const float* __restrict__ ppb2,
    float* __restrict__ out)
{
    extern __shared__ char smem[];
    const uint32_t sb = smem_u32(smem);
    const int tid = threadIdx.x;
    const int wid = tid >> 5, lane = tid & 31;
    const int wm = wid & 1, wn = wid >> 1;
    const int m0 = blockIdx.x * 32;

    const uint32_t sA = sb + N2_B0;
    const uint32_t sB = sb + N2_B0 + N2_SLOT;

    float acc[2][4];
    #pragma unroll
    for (int st = 0; st < 2; st++)
        #pragma unroll
        for (int r = 0; r < 4; r++) acc[st][r] = 0.f;

    load_Bw_cp(sA, N2_BPL, npbh, npbl, 128, 128, 256, 128, NSTR2, tid, 512); CP_COMMIT();
    load_Bw_cp(sB, N2_BPL, p0bHi, p0bLo, 128, 128, 128, 0, NSTR2, tid, 512); CP_COMMIT();

    load_A_agg(smem, m0, agg1, tid);

    // P1: agg1 @ np_bot; epi: +npb +npc +nf1 -> repack (nf2)
    CP_WAIT1(); __syncthreads();
    mma_span16(sb, sb + N2_ALO, sA, sA + N2_BPL, NSTR2, NSTR2, 8, acc, wm, wn, lane);
    __syncthreads();
    epi_repack16(smem, NSTR2, N2_ALO, acc, m0, wm, npb, npc, nf1, nullptr, wn, lane);
    load_Bw_cp(sA, N2_BPL, p1Hi, p1Lo, 128, 128, 128, 0, NSTR2, tid, 512); CP_COMMIT();

    // P2: nf2 @ pp0b; epi: +ppb0 +pc -> repack (h1)
    CP_WAIT1(); __syncthreads();
    mma_span16(sb, sb + N2_ALO, sB, sB + N2_BPL, NSTR2, NSTR2, 8, acc, wm, wn, lane);
    __syncthreads();
    epi_repack16(smem, NSTR2, N2_ALO, acc, m0, wm, ppb0, pc, nullptr, nullptr, wn, lane);

    // P3: h1 @ pp1 -> h2 stage
    CP_WAIT0(); __syncthreads();
    mma_span16(sb, sb + N2_ALO, sA, sA + N2_BPL, NSTR2, NSTR2, 8, acc, wm, wn, lane);
    __syncthreads();
    float* stage = (float*)(smem + N2_B0);
    #pragma unroll
    for (int st = 0; st < 2; st++) {
        int n = wn * 16 + st * 8 + ((lane & 3) << 1);
        float b0 = __ldg(ppb1 + n), b1 = __ldg(ppb1 + n + 1);
        int r0 = wm * 16 + (lane >> 2);
        #pragma unroll
        for (int h = 0; h < 2; h++) {
            int r = r0 + h * 8;
            stage[r * 132 + n]     = fmaxf(acc[st][h * 2 + 0] + b0, 0.f);
            stage[r * 132 + n + 1] = fmaxf(acc[st][h * 2 + 1] + b1, 0.f);
        }
    }
    __syncthreads();
    if (tid < 96) {
        int m = tid / 3, n = tid - (tid / 3) * 3;
        const float* aa = stage + m * 132;
        float s = __ldg(ppb2 + n);
        #pragma unroll 16
        for (int k = 0; k < 128; k++) s += aa[k] * __ldg(ppW2 + k * 3 + n);
        out[(size_t)(m0 + m) * 3 + n] = s;
    }
}

// ---------------- launch ----------------
extern "C" void kernel_launch(void* const* d_in, const int* in_sizes, int n_in,
                              void* d_out, int out_size)
{
    const float* x    = (const float*)d_in[0];
    const float* Rr   = (const float*)d_in[1];
    const float* Rs   = (const float*)d_in[2];
    const float* neW0 = (const float*)d_in[4];  const float* neb0 = (const float*)d_in[5];
    const float* neW1 = (const float*)d_in[6];  const float* neb1 = (const float*)d_in[7];
    const float* neW2 = (const float*)d_in[8];  const float* neb2 = (const float*)d_in[9];
    const float* eeW0 = (const float*)d_in[10]; const float* eeb0 = (const float*)d_in[11];
    const float* eeW1 = (const float*)d_in[12]; const float* eeb1 = (const float*)d_in[13];
    const float* eeW2 = (const float*)d_in[14]; const float* eeb2 = (const float*)d_in[15];
    const float* npW  = (const float*)d_in[16]; const float* npb  = (const float*)d_in[17];
    const float* epW  = (const float*)d_in[18]; const float* epb  = (const float*)d_in[19];
    const float* ppW0 = (const float*)d_in[20]; const float* ppb0 = (const float*)d_in[21];
    const float* ppW1 = (const float*)d_in[22]; const float* ppb1 = (const float*)d_in[23];
    const float* ppW2 = (const float*)d_in[24]; const float* ppb2 = (const float*)d_in[25];
    float* out = (float*)d_out;

    uint32_t* arena; cudaGetSymbolAddress((void**)&arena, g_arena);
    int* recv; cudaGetSymbolAddress((void**)&recv, g_recv);
    int* send; cudaGetSymbolAddress((void**)&send, g_send);
    __nv_bfloat16* whi; cudaGetSymbolAddress((void**)&whi, g_whi);
    __nv_bfloat16* wlo; cudaGetSymbolAddress((void**)&wlo, g_wlo);

    uint32_t* neb    = arena + OFF_NEB;
    float*    nef    = (float*)(arena + OFF_NEF);
    float*    nf1f   = (float*)(arena + OFF_NF1F);
    float*    pc     = (float*)(arena + OFF_PC);
    float*    npc    = (float*)(arena + OFF_NPC);
    float*    agg0   = (float*)(arena + OFF_AGG0);
    float*    agg1   = (float*)(arena + OFF_AGG1);
    float*    prs    = (float*)(arena + OFF_PRS);
    float*    prpspA = (float*)(arena + OFF_PRPSPA);
    float*    prpspB = (float*)(arena + OFF_PRPSPB);
    float*    ec     = (float*)(arena + OFF_EC);

    const int WO[12] = {0,8192,24576,40960,57344,73728,90112,106496,139264,172032,188416,204800};

    static bool s_init = false;
    static cudaStream_t s1, s2;
    static cudaEvent_t evStart, evPrep, evS1, evNE;
    if (!s_init) {
        cudaStreamCreateWithFlags(&s1, cudaStreamNonBlocking);
        cudaStreamCreateWithFlags(&s2, cudaStreamNonBlocking);
        cudaEventCreateWithFlags(&evStart, cudaEventDisableTiming);
        cudaEventCreateWithFlags(&evPrep,  cudaEventDisableTiming);
        cudaEventCreateWithFlags(&evS1,    cudaEventDisableTiming);
        cudaEventCreateWithFlags(&evNE,    cudaEventDisableTiming);
        cudaFuncSetAttribute(node_mega,       cudaFuncAttributeMaxDynamicSharedMemorySize, NM_SMEM);
        cudaFuncSetAttribute(edge_mega,       cudaFuncAttributeMaxDynamicSharedMemorySize, EM_SMEM);
        cudaFuncSetAttribute(np_prpsp_kernel, cudaFuncAttributeMaxDynamicSharedMemorySize, NT_SMEM);
        cudaFuncSetAttribute(tail_kernel,     cudaFuncAttributeMaxDynamicSharedMemorySize, NT_SMEM);
        s_init = true;
    }

    // fork at root: extract + agg zeros on s1
    cudaEventRecord(evStart, 0);
    cudaStreamWaitEvent(s1, evStart, 0);
    extract_idx2_kernel<<<2 * BE / 8, 256, 0, s1>>>(Rr, Rs, recv, send);
    cudaMemsetAsync(agg0, 0, (size_t)2 * BN * 128 * sizeof(float), s1);
    cudaEventRecord(evS1, s1);

    // origin: weight prep
    PArg pa;
    pa.W[0] = neW0; pa.W[1] = neW1; pa.W[2] = neW2;
    pa.W[3] = eeW0; pa.W[4] = eeW1; pa.W[5] = eeW2;
    pa.W[6] = epW;  pa.W[7] = epW;  pa.W[8] = npW;
    pa.W[9] = ppW0; pa.W[10] = ppW0; pa.W[11] = ppW1;
    prep_weights<<<dim3(12, 8), 256>>>(pa, whi, wlo);
    cudaEventRecord(evPrep, 0);
    cudaStreamWaitEvent(s2, evPrep, 0);

    // s2: fused node mega-chain (PrPs + encoder + projections + pc + npc), 256 threads
    {
        NodeArg na;
        na.x = x;
        na.eerh = whi + WO[3];        na.eerl = wlo + WO[3];
        na.eesh = whi + WO[3] + 8192; na.eesl = wlo + WO[3] + 8192;
        na.w0h = whi + WO[0]; na.w0l = wlo + WO[0];
        na.w1h = whi + WO[1]; na.w1l = wlo + WO[1];
        na.w2h = whi + WO[2]; na.w2l = wlo + WO[2];
        na.eprh = whi + WO[7];          na.eprl = wlo + WO[7];
        na.epsh = whi + WO[7] + 16384;  na.epsl = wlo + WO[7] + 16384;
        na.pqh = whi + WO[9];  na.pql = wlo + WO[9];
        na.nph = whi + WO[8];  na.npl = wlo + WO[8];
        na.b0 = neb0; na.b1 = neb1; na.b2 = neb2;
        na.neb = neb; na.nef = nef; na.prs = prs; na.prpsp = prpspA;
        na.pc = pc; na.npc = npc;
        node_mega<<<BN / 32, 256, NM_SMEM, s2>>>(na);
    }
    cudaEventRecord(evNE, s2);

    // join: indices + node outputs
    cudaStreamWaitEvent(0, evS1, 0);
    cudaStreamWaitEvent(0, evNE, 0);

    // fused edge chain + step-0 scatter (128-row tiles, mt=4, 256 threads)
    {
        EdgeArg ea;
        ea.prs = prs; ea.recv = recv; ea.send = send; ea.eeb0 = eeb0;
        ea.w1h = whi + WO[4]; ea.w1l = wlo + WO[4];
        ea.w2h = whi + WO[5]; ea.w2l = wlo + WO[5];
        ea.weh = whi + WO[6]; ea.wel = wlo + WO[6];
        ea.b1 = eeb1; ea.b2 = eeb2;
        ea.prpsp = prpspA; ea.epb = epb;
        ea.ec = ec; ea.agg = agg0;
        edge_mega<<<BE / 128, 256, EM_SMEM>>>(ea);
    }

    // fused np(step0) + prpsp(step1): np_bot only (npc precomputed)
    np_prpsp_kernel<<<BN / 32, 512, NT_SMEM>>>(agg0, npc, nef,
        whi + WO[8], wlo + WO[8], npb, whi + WO[7], wlo + WO[7],
        nf1f, prpspB);

    // step-1 scatter (vectorized, v4 reductions)
    fused_scatter_kernel<<<BE * 32 / 256, 256>>>(ec, prpspB, recv, send, epb, agg1);

    // fused np(step1) + predictor + output: np_bot only
    tail_kernel<<<BN / 32, 512, NT_SMEM>>>(agg1, npc, nf1f,
        whi + WO[8], wlo + WO[8], npb, pc,
        whi + WO[10], wlo + WO[10], ppb0,
        whi + WO[11], wlo + WO[11], ppb1,
        ppW2, ppb2, out);
}